// round 5
// baseline (speedup 1.0000x reference)
#include <cuda_runtime.h>
#include <cuda_fp16.h>
#include <cstdint>

// Problem dims (fixed by reference)
#define DIN   4096
#define DOUT  4096
#define MTOT  8192
#define QG    128
#define NGRP  (DIN / QG)

// GEMM tiling: CTA 128(M) x 256(N), warp 64x64, KB=32, 3 stages
#define MT     128
#define NT     256
#define KB     32
#define NKIT   (DIN / KB)     // 128
#define STAGES 3
#define ROWB   80             // 64B data + 16B pad (odd multiple of 16)
#define STG_BYTES ((MT + NT) * ROWB)        // 30720
#define SMEM_TOTAL (STAGES * STG_BYTES)     // 92160

// ------------------------- device scratch (no cudaMalloc allowed) ----------
__device__ __half g_xq[(size_t)MTOT * DIN];   // quantized activations (exact ints in fp16)
__device__ __half g_wq[(size_t)DOUT * DIN];   // dequantized weights in fp16
__device__ float  g_sx[MTOT];                 // per-token activation scale
__device__ float  g_scale[DIN];               // clip(exp(log_scale))

// ------------------------- helpers -----------------------------------------
__device__ __forceinline__ uint32_t smem_u32(const void* p) {
    uint32_t a;
    asm("{ .reg .u64 t; cvta.to.shared.u64 t, %1; cvt.u32.u64 %0, t; }" : "=r"(a) : "l"(p));
    return a;
}
__device__ __forceinline__ void cp16(uint32_t dst, const void* src) {
    asm volatile("cp.async.cg.shared.global [%0], [%1], 16;" :: "r"(dst), "l"(src));
}
__device__ __forceinline__ void ldm4(uint32_t* r, uint32_t a) {
    asm volatile("ldmatrix.sync.aligned.m8n8.x4.shared.b16 {%0,%1,%2,%3}, [%4];"
                 : "=r"(r[0]), "=r"(r[1]), "=r"(r[2]), "=r"(r[3]) : "r"(a));
}
__device__ __forceinline__ void mma16816(float* c, const uint32_t* a, const uint32_t* b) {
    asm volatile(
        "mma.sync.aligned.m16n8k16.row.col.f32.f16.f16.f32 "
        "{%0,%1,%2,%3}, {%4,%5,%6,%7}, {%8,%9}, {%0,%1,%2,%3};"
        : "+f"(c[0]), "+f"(c[1]), "+f"(c[2]), "+f"(c[3])
        : "r"(a[0]), "r"(a[1]), "r"(a[2]), "r"(a[3]), "r"(b[0]), "r"(b[1]));
}

// ------------------------- kernel 1: scale ---------------------------------
__global__ void k_scale(const float* __restrict__ ls) {
    int i = blockIdx.x * blockDim.x + threadIdx.x;
    if (i < DIN) {
        float s = expf(ls[i]);
        g_scale[i] = fminf(fmaxf(s, 1e-4f), 1e4f);
    }
}

// ------------------------- kernel 2: weight fake-quant -> fp16 -------------
__global__ __launch_bounds__(256) void k_wq(const float* __restrict__ w) {
    int wid = threadIdx.x >> 5, lane = threadIdx.x & 31;
    int gid = blockIdx.x * 8 + wid;
    int row = gid >> 5;
    int grp = gid & 31;
    int k0  = grp * QG + lane * 4;

    float4 wv = *(const float4*)(w + (size_t)row * DIN + k0);
    float4 sc = *(const float4*)(g_scale + k0);
    float v0 = wv.x * sc.x, v1 = wv.y * sc.y, v2 = wv.z * sc.z, v3 = wv.w * sc.w;

    float mx = fmaxf(fmaxf(v0, v1), fmaxf(v2, v3));
    float mn = fminf(fminf(v0, v1), fminf(v2, v3));
    #pragma unroll
    for (int o = 16; o; o >>= 1) {
        mx = fmaxf(mx, __shfl_xor_sync(0xFFFFFFFFu, mx, o));
        mn = fminf(mn, __shfl_xor_sync(0xFFFFFFFFu, mn, o));
    }
    float s = fmaxf(mx - mn, 1e-5f) / 15.0f;
    float z = fminf(fmaxf(-rintf(mn / s), 0.0f), 15.0f);

    float q0 = (fminf(fmaxf(rintf(v0 / s) + z, 0.0f), 15.0f) - z) * s;
    float q1 = (fminf(fmaxf(rintf(v1 / s) + z, 0.0f), 15.0f) - z) * s;
    float q2 = (fminf(fmaxf(rintf(v2 / s) + z, 0.0f), 15.0f) - z) * s;
    float q3 = (fminf(fmaxf(rintf(v3 / s) + z, 0.0f), 15.0f) - z) * s;

    __half2* dst = (__half2*)(g_wq + (size_t)row * DIN + k0);
    dst[0] = __halves2half2(__float2half_rn(q0), __float2half_rn(q1));
    dst[1] = __halves2half2(__float2half_rn(q2), __float2half_rn(q3));
}

// ------------------------- kernel 3: activation fake-quant -----------------
__global__ __launch_bounds__(256) void k_aq(const float* __restrict__ x) {
    int t = blockIdx.x, tid = threadIdx.x;
    int wid = tid >> 5, lane = tid & 31;
    __shared__ float red[8];

    float v[16];
    float m = 0.0f;
    #pragma unroll
    for (int i = 0; i < 4; i++) {
        int k = (i * 256 + tid) * 4;
        float4 xv = *(const float4*)(x + (size_t)t * DIN + k);
        float4 sc = *(const float4*)(g_scale + k);
        v[i * 4 + 0] = xv.x / sc.x;
        v[i * 4 + 1] = xv.y / sc.y;
        v[i * 4 + 2] = xv.z / sc.z;
        v[i * 4 + 3] = xv.w / sc.w;
        m = fmaxf(m, fmaxf(fmaxf(fabsf(v[i*4+0]), fabsf(v[i*4+1])),
                           fmaxf(fabsf(v[i*4+2]), fabsf(v[i*4+3]))));
    }
    #pragma unroll
    for (int o = 16; o; o >>= 1) m = fmaxf(m, __shfl_xor_sync(0xFFFFFFFFu, m, o));
    if (lane == 0) red[wid] = m;
    __syncthreads();
    if (wid == 0) {
        float tmx = red[lane & 7];
        #pragma unroll
        for (int o = 4; o; o >>= 1) tmx = fmaxf(tmx, __shfl_xor_sync(0xFFFFFFFFu, tmx, o));
        if (lane == 0) red[0] = tmx;
    }
    __syncthreads();
    float s = fmaxf(red[0], 1e-5f) / 127.0f;
    if (tid == 0) g_sx[t] = s;

    #pragma unroll
    for (int i = 0; i < 4; i++) {
        int k = (i * 256 + tid) * 4;
        float q0 = fminf(fmaxf(rintf(v[i*4+0] / s), -128.0f), 127.0f);
        float q1 = fminf(fmaxf(rintf(v[i*4+1] / s), -128.0f), 127.0f);
        float q2 = fminf(fmaxf(rintf(v[i*4+2] / s), -128.0f), 127.0f);
        float q3 = fminf(fmaxf(rintf(v[i*4+3] / s), -128.0f), 127.0f);
        __half2* dst = (__half2*)(g_xq + (size_t)t * DIN + k);
        dst[0] = __halves2half2(__float2half_rn(q0), __float2half_rn(q1));
        dst[1] = __halves2half2(__float2half_rn(q2), __float2half_rn(q3));
    }
}

// ------------------------- kernel 4: GEMM (mma.sync + cp.async) ------------
// per stage: A 128 rows x 64B (512 cp16, 2/thread), B 256 rows x 64B (1024 cp16, 4/thread)
__device__ __forceinline__ void issue_stage(uint32_t sb, int m0, int n0, int kb,
                                            int s, int tid) {
    uint32_t sA = sb + s * STG_BYTES;
    uint32_t sB = sA + MT * ROWB;
    #pragma unroll
    for (int j = 0; j < 2; j++) {          // A
        int seg = tid + j * 256;
        int r = seg >> 2, c = seg & 3;
        cp16(sA + r * ROWB + c * 16, g_xq + (size_t)(m0 + r) * DIN + kb * KB + c * 8);
    }
    #pragma unroll
    for (int j = 0; j < 4; j++) {          // B
        int seg = tid + j * 256;
        int r = seg >> 2, c = seg & 3;
        cp16(sB + r * ROWB + c * 16, g_wq + (size_t)(n0 + r) * DIN + kb * KB + c * 8);
    }
    asm volatile("cp.async.commit_group;" ::: "memory");
}

__global__ __launch_bounds__(256, 1) void k_gemm(const float* __restrict__ bias,
                                                 float* __restrict__ out) {
    extern __shared__ char smem[];
    const uint32_t sb = smem_u32(smem);
    int tid = threadIdx.x, lane = tid & 31, wid = tid >> 5;
    int wm = wid & 1, wn = wid >> 1;          // warp grid 2(m) x 4(n), warp tile 64x64
    int bid = blockIdx.x;
    int nt = bid & 15, mt = bid >> 4;         // 16 n-tiles, 64 m-tiles
    int m0 = mt * MT, n0 = nt * NT;

    // prologue: stages 0,1
    issue_stage(sb, m0, n0, 0, 0, tid);
    issue_stage(sb, m0, n0, 1, 1, tid);

    float c[4][8][4];
    #pragma unroll
    for (int i = 0; i < 4; i++)
        #pragma unroll
        for (int j = 0; j < 8; j++)
            #pragma unroll
            for (int k = 0; k < 4; k++) c[i][j][k] = 0.0f;

    int s = 0;
    for (int kb = 0; kb < NKIT; kb++) {
        asm volatile("cp.async.wait_group 1;" ::: "memory");
        __syncthreads();

        if (kb + 2 < NKIT) {
            int s2 = s + 2; if (s2 >= STAGES) s2 -= STAGES;
            issue_stage(sb, m0, n0, kb + 2, s2, tid);
        } else {
            asm volatile("cp.async.commit_group;" ::: "memory");
        }

        uint32_t sA = sb + s * STG_BYTES;
        uint32_t sB = sA + MT * ROWB;

        #pragma unroll
        for (int ks = 0; ks < 2; ks++) {
            uint32_t a[4][4], b[8][2];
            #pragma unroll
            for (int mi = 0; mi < 4; mi++) {
                uint32_t addr = sA + (uint32_t)(wm * 64 + mi * 16 + (lane & 15)) * ROWB
                              + ks * 32 + ((lane >> 4) << 4);
                ldm4(a[mi], addr);
            }
            #pragma unroll
            for (int nj = 0; nj < 4; nj++) {
                uint32_t r[4];
                int g = lane >> 3;
                uint32_t addr = sB + (uint32_t)(wn * 64 + nj * 16 + ((g >> 1) << 3) + (lane & 7)) * ROWB
                              + ks * 32 + ((g & 1) << 4);
                ldm4(r, addr);
                b[nj * 2][0] = r[0]; b[nj * 2][1] = r[1];
                b[nj * 2 + 1][0] = r[2]; b[nj * 2 + 1][1] = r[3];
            }
            #pragma unroll
            for (int mi = 0; mi < 4; mi++)
                #pragma unroll
                for (int ni = 0; ni < 8; ni++)
                    mma16816(c[mi][ni], a[mi], b[ni]);
        }
        s = (s + 1 == STAGES) ? 0 : s + 1;
    }

    // ---------------- epilogue: out = D * s_x[m] + bias[n] -----------------
    int qr = lane >> 2, qc = lane & 3;
    #pragma unroll
    for (int mi = 0; mi < 4; mi++) {
        int row0 = m0 + wm * 64 + mi * 16 + qr;
        float sx0 = g_sx[row0], sx1 = g_sx[row0 + 8];
        #pragma unroll
        for (int ni = 0; ni < 8; ni++) {
            int col = n0 + wn * 64 + ni * 8 + 2 * qc;
            float2 bv = *(const float2*)(bias + col);
            float2 o0, o1;
            o0.x = c[mi][ni][0] * sx0 + bv.x;
            o0.y = c[mi][ni][1] * sx0 + bv.y;
            o1.x = c[mi][ni][2] * sx1 + bv.x;
            o1.y = c[mi][ni][3] * sx1 + bv.y;
            *(float2*)(out + (size_t)row0 * DOUT + col) = o0;
            *(float2*)(out + (size_t)(row0 + 8) * DOUT + col) = o1;
        }
    }
}

// ------------------------- launch ------------------------------------------
extern "C" void kernel_launch(void* const* d_in, const int* in_sizes, int n_in,
                              void* d_out, int out_size) {
    (void)in_sizes; (void)n_in; (void)out_size;
    const float* x    = (const float*)d_in[0];
    const float* w    = (const float*)d_in[1];
    const float* bias = (const float*)d_in[2];
    const float* ls   = (const float*)d_in[3];
    float* out = (float*)d_out;

    k_scale<<<16, 256>>>(ls);
    k_wq<<<(DOUT * NGRP) / 8, 256>>>(w);
    k_aq<<<MTOT, 256>>>(x);

    cudaFuncSetAttribute(k_gemm, cudaFuncAttributeMaxDynamicSharedMemorySize, SMEM_TOTAL);
    k_gemm<<<(MTOT / MT) * (DOUT / NT), 256, SMEM_TOTAL>>>(bias, out);
}

// round 6
// speedup vs baseline: 1.1601x; 1.1601x over previous
#include <cuda_runtime.h>
#include <cuda_fp16.h>
#include <cstdint>

// Problem dims (fixed by reference)
#define DIN   4096
#define DOUT  4096
#define MTOT  8192
#define QG    128
#define NGRP  (DIN / QG)

// GEMM tiling: CTA 128x128, 4 warps (2x2), warp tile 64x64, KB=64, 3 stages
#define MT     128
#define NT     128
#define KB     64
#define NKIT   (DIN / KB)     // 64
#define STAGES 3
#define ROWB   144            // 128B data + 16B pad (odd multiple of 16)
#define STG_BYTES ((MT + NT) * ROWB)        // 36864
#define SMEM_TOTAL (STAGES * STG_BYTES)     // 110592

// ------------------------- device scratch (no cudaMalloc allowed) ----------
__device__ __half g_xq[(size_t)MTOT * DIN];   // quantized activations (exact ints in fp16)
__device__ __half g_wq[(size_t)DOUT * DIN];   // dequantized weights in fp16
__device__ float  g_sx[MTOT];                 // per-token activation scale
__device__ float  g_scale[DIN];               // clip(exp(log_scale))

// ------------------------- helpers -----------------------------------------
__device__ __forceinline__ uint32_t smem_u32(const void* p) {
    uint32_t a;
    asm("{ .reg .u64 t; cvta.to.shared.u64 t, %1; cvt.u32.u64 %0, t; }" : "=r"(a) : "l"(p));
    return a;
}
__device__ __forceinline__ void cp16(uint32_t dst, const void* src) {
    asm volatile("cp.async.cg.shared.global [%0], [%1], 16;" :: "r"(dst), "l"(src));
}
__device__ __forceinline__ void ldm4(uint32_t* r, uint32_t a) {
    asm volatile("ldmatrix.sync.aligned.m8n8.x4.shared.b16 {%0,%1,%2,%3}, [%4];"
                 : "=r"(r[0]), "=r"(r[1]), "=r"(r[2]), "=r"(r[3]) : "r"(a));
}
__device__ __forceinline__ void mma16816(float* c, const uint32_t* a, const uint32_t* b) {
    asm volatile(
        "mma.sync.aligned.m16n8k16.row.col.f32.f16.f16.f32 "
        "{%0,%1,%2,%3}, {%4,%5,%6,%7}, {%8,%9}, {%0,%1,%2,%3};"
        : "+f"(c[0]), "+f"(c[1]), "+f"(c[2]), "+f"(c[3])
        : "r"(a[0]), "r"(a[1]), "r"(a[2]), "r"(a[3]), "r"(b[0]), "r"(b[1]));
}

// ------------------------- kernel 1: scale ---------------------------------
__global__ void k_scale(const float* __restrict__ ls) {
    int i = blockIdx.x * blockDim.x + threadIdx.x;
    if (i < DIN) {
        float s = expf(ls[i]);
        g_scale[i] = fminf(fmaxf(s, 1e-4f), 1e4f);
    }
}

// ------------------------- kernel 2: weight fake-quant -> fp16 -------------
__global__ __launch_bounds__(256) void k_wq(const float* __restrict__ w) {
    int wid = threadIdx.x >> 5, lane = threadIdx.x & 31;
    int gid = blockIdx.x * 8 + wid;
    int row = gid >> 5;
    int grp = gid & 31;
    int k0  = grp * QG + lane * 4;

    float4 wv = *(const float4*)(w + (size_t)row * DIN + k0);
    float4 sc = *(const float4*)(g_scale + k0);
    float v0 = wv.x * sc.x, v1 = wv.y * sc.y, v2 = wv.z * sc.z, v3 = wv.w * sc.w;

    float mx = fmaxf(fmaxf(v0, v1), fmaxf(v2, v3));
    float mn = fminf(fminf(v0, v1), fminf(v2, v3));
    #pragma unroll
    for (int o = 16; o; o >>= 1) {
        mx = fmaxf(mx, __shfl_xor_sync(0xFFFFFFFFu, mx, o));
        mn = fminf(mn, __shfl_xor_sync(0xFFFFFFFFu, mn, o));
    }
    float s = fmaxf(mx - mn, 1e-5f) / 15.0f;
    float z = fminf(fmaxf(-rintf(mn / s), 0.0f), 15.0f);

    float q0 = (fminf(fmaxf(rintf(v0 / s) + z, 0.0f), 15.0f) - z) * s;
    float q1 = (fminf(fmaxf(rintf(v1 / s) + z, 0.0f), 15.0f) - z) * s;
    float q2 = (fminf(fmaxf(rintf(v2 / s) + z, 0.0f), 15.0f) - z) * s;
    float q3 = (fminf(fmaxf(rintf(v3 / s) + z, 0.0f), 15.0f) - z) * s;

    __half2* dst = (__half2*)(g_wq + (size_t)row * DIN + k0);
    dst[0] = __halves2half2(__float2half_rn(q0), __float2half_rn(q1));
    dst[1] = __halves2half2(__float2half_rn(q2), __float2half_rn(q3));
}

// ------------------------- kernel 3: activation fake-quant -----------------
__global__ __launch_bounds__(256) void k_aq(const float* __restrict__ x) {
    int t = blockIdx.x, tid = threadIdx.x;
    int wid = tid >> 5, lane = tid & 31;
    __shared__ float red[8];

    float v[16];
    float m = 0.0f;
    #pragma unroll
    for (int i = 0; i < 4; i++) {
        int k = (i * 256 + tid) * 4;
        float4 xv = *(const float4*)(x + (size_t)t * DIN + k);
        float4 sc = *(const float4*)(g_scale + k);
        v[i * 4 + 0] = xv.x / sc.x;
        v[i * 4 + 1] = xv.y / sc.y;
        v[i * 4 + 2] = xv.z / sc.z;
        v[i * 4 + 3] = xv.w / sc.w;
        m = fmaxf(m, fmaxf(fmaxf(fabsf(v[i*4+0]), fabsf(v[i*4+1])),
                           fmaxf(fabsf(v[i*4+2]), fabsf(v[i*4+3]))));
    }
    #pragma unroll
    for (int o = 16; o; o >>= 1) m = fmaxf(m, __shfl_xor_sync(0xFFFFFFFFu, m, o));
    if (lane == 0) red[wid] = m;
    __syncthreads();
    if (wid == 0) {
        float tmx = red[lane & 7];
        #pragma unroll
        for (int o = 4; o; o >>= 1) tmx = fmaxf(tmx, __shfl_xor_sync(0xFFFFFFFFu, tmx, o));
        if (lane == 0) red[0] = tmx;
    }
    __syncthreads();
    float s = fmaxf(red[0], 1e-5f) / 127.0f;
    if (tid == 0) g_sx[t] = s;

    #pragma unroll
    for (int i = 0; i < 4; i++) {
        int k = (i * 256 + tid) * 4;
        float q0 = fminf(fmaxf(rintf(v[i*4+0] / s), -128.0f), 127.0f);
        float q1 = fminf(fmaxf(rintf(v[i*4+1] / s), -128.0f), 127.0f);
        float q2 = fminf(fmaxf(rintf(v[i*4+2] / s), -128.0f), 127.0f);
        float q3 = fminf(fmaxf(rintf(v[i*4+3] / s), -128.0f), 127.0f);
        __half2* dst = (__half2*)(g_xq + (size_t)t * DIN + k);
        dst[0] = __halves2half2(__float2half_rn(q0), __float2half_rn(q1));
        dst[1] = __halves2half2(__float2half_rn(q2), __float2half_rn(q3));
    }
}

// ------------------------- kernel 4: GEMM (mma.sync + cp.async) ------------
// per stage (128 threads): A 128 rows x 128B (1024 cp16, 8/thr), B same
__device__ __forceinline__ void issue_stage(uint32_t sb, int m0, int n0, int kb,
                                            int s, int tid) {
    uint32_t sA = sb + s * STG_BYTES;
    uint32_t sB = sA + MT * ROWB;
    #pragma unroll
    for (int j = 0; j < 8; j++) {          // A
        int seg = tid + j * 128;
        int r = seg >> 3, c = seg & 7;
        cp16(sA + r * ROWB + c * 16, g_xq + (size_t)(m0 + r) * DIN + kb * KB + c * 8);
    }
    #pragma unroll
    for (int j = 0; j < 8; j++) {          // B
        int seg = tid + j * 128;
        int r = seg >> 3, c = seg & 7;
        cp16(sB + r * ROWB + c * 16, g_wq + (size_t)(n0 + r) * DIN + kb * KB + c * 8);
    }
    asm volatile("cp.async.commit_group;" ::: "memory");
}

__global__ __launch_bounds__(128, 2) void k_gemm(const float* __restrict__ bias,
                                                 float* __restrict__ out) {
    extern __shared__ char smem[];
    const uint32_t sb = smem_u32(smem);
    int tid = threadIdx.x, lane = tid & 31, wid = tid >> 5;
    int wm = wid & 1, wn = wid >> 1;          // warp grid 2(m) x 2(n), warp tile 64x64
    int bid = blockIdx.x;
    int nt = bid & 31, mt = bid >> 5;
    int m0 = mt * MT, n0 = nt * NT;

    // prologue: stages 0,1
    issue_stage(sb, m0, n0, 0, 0, tid);
    issue_stage(sb, m0, n0, 1, 1, tid);

    float c[4][8][4];
    #pragma unroll
    for (int i = 0; i < 4; i++)
        #pragma unroll
        for (int j = 0; j < 8; j++)
            #pragma unroll
            for (int k = 0; k < 4; k++) c[i][j][k] = 0.0f;

    int s = 0;
    for (int kb = 0; kb < NKIT; kb++) {
        asm volatile("cp.async.wait_group 1;" ::: "memory");
        __syncthreads();

        if (kb + 2 < NKIT) {
            int s2 = s + 2; if (s2 >= STAGES) s2 -= STAGES;
            issue_stage(sb, m0, n0, kb + 2, s2, tid);
        } else {
            asm volatile("cp.async.commit_group;" ::: "memory");
        }

        uint32_t sA = sb + s * STG_BYTES;
        uint32_t sB = sA + MT * ROWB;

        #pragma unroll
        for (int ks = 0; ks < 4; ks++) {
            uint32_t a[4][4], b[8][2];
            #pragma unroll
            for (int mi = 0; mi < 4; mi++) {
                uint32_t addr = sA + (uint32_t)(wm * 64 + mi * 16 + (lane & 15)) * ROWB
                              + ks * 32 + ((lane >> 4) << 4);
                ldm4(a[mi], addr);
            }
            #pragma unroll
            for (int nj = 0; nj < 4; nj++) {
                uint32_t r[4];
                int g = lane >> 3;
                uint32_t addr = sB + (uint32_t)(wn * 64 + nj * 16 + ((g >> 1) << 3) + (lane & 7)) * ROWB
                              + ks * 32 + ((g & 1) << 4);
                ldm4(r, addr);
                b[nj * 2][0] = r[0]; b[nj * 2][1] = r[1];
                b[nj * 2 + 1][0] = r[2]; b[nj * 2 + 1][1] = r[3];
            }
            #pragma unroll
            for (int mi = 0; mi < 4; mi++)
                #pragma unroll
                for (int ni = 0; ni < 8; ni++)
                    mma16816(c[mi][ni], a[mi], b[ni]);
        }
        s = (s + 1 == STAGES) ? 0 : s + 1;
    }

    // ---------------- epilogue: out = D * s_x[m] + bias[n] -----------------
    int qr = lane >> 2, qc = lane & 3;
    #pragma unroll
    for (int mi = 0; mi < 4; mi++) {
        int row0 = m0 + wm * 64 + mi * 16 + qr;
        float sx0 = g_sx[row0], sx1 = g_sx[row0 + 8];
        #pragma unroll
        for (int ni = 0; ni < 8; ni++) {
            int col = n0 + wn * 64 + ni * 8 + 2 * qc;
            float2 bv = *(const float2*)(bias + col);
            float2 o0, o1;
            o0.x = c[mi][ni][0] * sx0 + bv.x;
            o0.y = c[mi][ni][1] * sx0 + bv.y;
            o1.x = c[mi][ni][2] * sx1 + bv.x;
            o1.y = c[mi][ni][3] * sx1 + bv.y;
            *(float2*)(out + (size_t)row0 * DOUT + col) = o0;
            *(float2*)(out + (size_t)(row0 + 8) * DOUT + col) = o1;
        }
    }
}

// ------------------------- launch ------------------------------------------
extern "C" void kernel_launch(void* const* d_in, const int* in_sizes, int n_in,
                              void* d_out, int out_size) {
    (void)in_sizes; (void)n_in; (void)out_size;
    const float* x    = (const float*)d_in[0];
    const float* w    = (const float*)d_in[1];
    const float* bias = (const float*)d_in[2];
    const float* ls   = (const float*)d_in[3];
    float* out = (float*)d_out;

    k_scale<<<16, 256>>>(ls);
    k_wq<<<(DOUT * NGRP) / 8, 256>>>(w);
    k_aq<<<MTOT, 256>>>(x);

    cudaFuncSetAttribute(k_gemm, cudaFuncAttributeMaxDynamicSharedMemorySize, SMEM_TOTAL);
    k_gemm<<<(MTOT / MT) * (DOUT / NT), 128, SMEM_TOTAL>>>(bias, out);
}

// round 7
// speedup vs baseline: 1.3507x; 1.1643x over previous
#include <cuda_runtime.h>
#include <cuda_fp16.h>
#include <cstdint>

// Problem dims (fixed by reference)
#define DIN   4096
#define DOUT  4096
#define MTOT  8192
#define QG    128
#define NGRP  (DIN / QG)

// GEMM tiling: CTA 128x128, 4 warps (2x2), warp tile 64x64, KB=64, 3 stages
#define MT     128
#define NT     128
#define KB     64
#define NKIT   (DIN / KB)     // 64
#define STAGES 3
#define ROWB   144            // 128B data + 16B pad (odd multiple of 16)
#define STG_BYTES ((MT + NT) * ROWB)        // 36864
#define SMEM_TOTAL (STAGES * STG_BYTES)     // 110592

// ------------------------- device scratch (no cudaMalloc allowed) ----------
__device__ __half g_xq[(size_t)MTOT * DIN];   // quantized activations (exact ints in fp16)
__device__ __half g_wq[(size_t)DOUT * DIN];   // dequantized weights in fp16
__device__ float  g_sx[MTOT];                 // per-token activation scale
__device__ float  g_scale[DIN];               // clip(exp(log_scale))

// ------------------------- helpers -----------------------------------------
__device__ __forceinline__ uint32_t smem_u32(const void* p) {
    uint32_t a;
    asm("{ .reg .u64 t; cvta.to.shared.u64 t, %1; cvt.u32.u64 %0, t; }" : "=r"(a) : "l"(p));
    return a;
}
__device__ __forceinline__ void cp16(uint32_t dst, const void* src) {
    asm volatile("cp.async.cg.shared.global [%0], [%1], 16;" :: "r"(dst), "l"(src));
}
__device__ __forceinline__ void ldm4(uint32_t* r, uint32_t a) {
    asm volatile("ldmatrix.sync.aligned.m8n8.x4.shared.b16 {%0,%1,%2,%3}, [%4];"
                 : "=r"(r[0]), "=r"(r[1]), "=r"(r[2]), "=r"(r[3]) : "r"(a));
}
__device__ __forceinline__ void mma16816(float* c, const uint32_t* a, const uint32_t* b) {
    asm volatile(
        "mma.sync.aligned.m16n8k16.row.col.f32.f16.f16.f32 "
        "{%0,%1,%2,%3}, {%4,%5,%6,%7}, {%8,%9}, {%0,%1,%2,%3};"
        : "+f"(c[0]), "+f"(c[1]), "+f"(c[2]), "+f"(c[3])
        : "r"(a[0]), "r"(a[1]), "r"(a[2]), "r"(a[3]), "r"(b[0]), "r"(b[1]));
}

// ------------------------- kernel 1: scale ---------------------------------
__global__ void k_scale(const float* __restrict__ ls) {
    int i = blockIdx.x * blockDim.x + threadIdx.x;
    if (i < DIN) {
        float s = expf(ls[i]);
        g_scale[i] = fminf(fmaxf(s, 1e-4f), 1e4f);
    }
}

// ------------------------- kernel 2: weight fake-quant -> fp16 -------------
__global__ __launch_bounds__(256) void k_wq(const float* __restrict__ w) {
    int wid = threadIdx.x >> 5, lane = threadIdx.x & 31;
    int gid = blockIdx.x * 8 + wid;
    int row = gid >> 5;
    int grp = gid & 31;
    int k0  = grp * QG + lane * 4;

    float4 wv = *(const float4*)(w + (size_t)row * DIN + k0);
    float4 sc = *(const float4*)(g_scale + k0);
    float v0 = wv.x * sc.x, v1 = wv.y * sc.y, v2 = wv.z * sc.z, v3 = wv.w * sc.w;

    float mx = fmaxf(fmaxf(v0, v1), fmaxf(v2, v3));
    float mn = fminf(fminf(v0, v1), fminf(v2, v3));
    #pragma unroll
    for (int o = 16; o; o >>= 1) {
        mx = fmaxf(mx, __shfl_xor_sync(0xFFFFFFFFu, mx, o));
        mn = fminf(mn, __shfl_xor_sync(0xFFFFFFFFu, mn, o));
    }
    float s = fmaxf(mx - mn, 1e-5f) / 15.0f;
    float z = fminf(fmaxf(-rintf(mn / s), 0.0f), 15.0f);

    float q0 = (fminf(fmaxf(rintf(v0 / s) + z, 0.0f), 15.0f) - z) * s;
    float q1 = (fminf(fmaxf(rintf(v1 / s) + z, 0.0f), 15.0f) - z) * s;
    float q2 = (fminf(fmaxf(rintf(v2 / s) + z, 0.0f), 15.0f) - z) * s;
    float q3 = (fminf(fmaxf(rintf(v3 / s) + z, 0.0f), 15.0f) - z) * s;

    __half2* dst = (__half2*)(g_wq + (size_t)row * DIN + k0);
    dst[0] = __halves2half2(__float2half_rn(q0), __float2half_rn(q1));
    dst[1] = __halves2half2(__float2half_rn(q2), __float2half_rn(q3));
}

// ------------------------- kernel 3: activation fake-quant -----------------
__global__ __launch_bounds__(256) void k_aq(const float* __restrict__ x) {
    int t = blockIdx.x, tid = threadIdx.x;
    int wid = tid >> 5, lane = tid & 31;
    __shared__ float red[8];

    float v[16];
    float m = 0.0f;
    #pragma unroll
    for (int i = 0; i < 4; i++) {
        int k = (i * 256 + tid) * 4;
        float4 xv = *(const float4*)(x + (size_t)t * DIN + k);
        float4 sc = *(const float4*)(g_scale + k);
        v[i * 4 + 0] = xv.x / sc.x;
        v[i * 4 + 1] = xv.y / sc.y;
        v[i * 4 + 2] = xv.z / sc.z;
        v[i * 4 + 3] = xv.w / sc.w;
        m = fmaxf(m, fmaxf(fmaxf(fabsf(v[i*4+0]), fabsf(v[i*4+1])),
                           fmaxf(fabsf(v[i*4+2]), fabsf(v[i*4+3]))));
    }
    #pragma unroll
    for (int o = 16; o; o >>= 1) m = fmaxf(m, __shfl_xor_sync(0xFFFFFFFFu, m, o));
    if (lane == 0) red[wid] = m;
    __syncthreads();
    if (wid == 0) {
        float tmx = red[lane & 7];
        #pragma unroll
        for (int o = 4; o; o >>= 1) tmx = fmaxf(tmx, __shfl_xor_sync(0xFFFFFFFFu, tmx, o));
        if (lane == 0) red[0] = tmx;
    }
    __syncthreads();
    float s = fmaxf(red[0], 1e-5f) / 127.0f;
    if (tid == 0) g_sx[t] = s;

    #pragma unroll
    for (int i = 0; i < 4; i++) {
        int k = (i * 256 + tid) * 4;
        float q0 = fminf(fmaxf(rintf(v[i*4+0] / s), -128.0f), 127.0f);
        float q1 = fminf(fmaxf(rintf(v[i*4+1] / s), -128.0f), 127.0f);
        float q2 = fminf(fmaxf(rintf(v[i*4+2] / s), -128.0f), 127.0f);
        float q3 = fminf(fmaxf(rintf(v[i*4+3] / s), -128.0f), 127.0f);
        __half2* dst = (__half2*)(g_xq + (size_t)t * DIN + k);
        dst[0] = __halves2half2(__float2half_rn(q0), __float2half_rn(q1));
        dst[1] = __halves2half2(__float2half_rn(q2), __float2half_rn(q3));
    }
}

// ------------------------- kernel 4: GEMM (mma.sync + cp.async, frag-pipelined)
// per stage (128 threads): A 128 rows x 128B (1024 cp16, 8/thr), B same
__device__ __forceinline__ void issue_stage(uint32_t sb, int m0, int n0, int kb,
                                            int s, int tid) {
    uint32_t sA = sb + s * STG_BYTES;
    uint32_t sB = sA + MT * ROWB;
    #pragma unroll
    for (int j = 0; j < 8; j++) {          // A
        int seg = tid + j * 128;
        int r = seg >> 3, c = seg & 7;
        cp16(sA + r * ROWB + c * 16, g_xq + (size_t)(m0 + r) * DIN + kb * KB + c * 8);
    }
    #pragma unroll
    for (int j = 0; j < 8; j++) {          // B
        int seg = tid + j * 128;
        int r = seg >> 3, c = seg & 7;
        cp16(sB + r * ROWB + c * 16, g_wq + (size_t)(n0 + r) * DIN + kb * KB + c * 8);
    }
    asm volatile("cp.async.commit_group;" ::: "memory");
}

__global__ __launch_bounds__(128, 2) void k_gemm(const float* __restrict__ bias,
                                                 float* __restrict__ out) {
    extern __shared__ char smem[];
    const uint32_t sb = smem_u32(smem);
    int tid = threadIdx.x, lane = tid & 31, wid = tid >> 5;
    int wm = wid & 1, wn = wid >> 1;          // warp grid 2(m) x 2(n), warp tile 64x64
    int bid = blockIdx.x;
    int nt = bid & 31, mt = bid >> 5;
    int m0 = mt * MT, n0 = nt * NT;

    // precomputed per-thread ldmatrix offsets (within a stage)
    uint32_t aoff[4], boff[4];
    #pragma unroll
    for (int mi = 0; mi < 4; mi++)
        aoff[mi] = (uint32_t)(wm * 64 + mi * 16 + (lane & 15)) * ROWB + ((lane >> 4) << 4);
    {
        int g = lane >> 3;
        #pragma unroll
        for (int nj = 0; nj < 4; nj++)
            boff[nj] = (uint32_t)(wn * 64 + nj * 16 + ((g >> 1) << 3) + (lane & 7)) * ROWB
                     + ((g & 1) << 4) + MT * ROWB;
    }

    // prologue: stages 0,1
    issue_stage(sb, m0, n0, 0, 0, tid);
    issue_stage(sb, m0, n0, 1, 1, tid);

    float c[4][8][4];
    #pragma unroll
    for (int i = 0; i < 4; i++)
        #pragma unroll
        for (int j = 0; j < 8; j++)
            #pragma unroll
            for (int k = 0; k < 4; k++) c[i][j][k] = 0.0f;

    uint32_t a[2][4][4], b[2][8][2];
    int s = 0;
    for (int kb = 0; kb < NKIT; kb++) {
        // stages kb and kb+1 are complete after this wait+sync
        asm volatile("cp.async.wait_group 0;" ::: "memory");
        __syncthreads();

        if (kb + 2 < NKIT) {
            int s2 = s + 2; if (s2 >= STAGES) s2 -= STAGES;
            issue_stage(sb, m0, n0, kb + 2, s2, tid);
        }

        uint32_t stg  = sb + s * STG_BYTES;
        int s1 = s + 1; if (s1 >= STAGES) s1 -= STAGES;
        uint32_t stgn = sb + s1 * STG_BYTES;

        if (kb == 0) {   // initial fragment load (stage 0, ks 0) into buf 0
            #pragma unroll
            for (int mi = 0; mi < 4; mi++) ldm4(a[0][mi], stg + aoff[mi]);
            #pragma unroll
            for (int nj = 0; nj < 4; nj++) {
                uint32_t r[4];
                ldm4(r, stg + boff[nj]);
                b[0][nj*2][0] = r[0]; b[0][nj*2][1] = r[1];
                b[0][nj*2+1][0] = r[2]; b[0][nj*2+1][1] = r[3];
            }
        }

        #pragma unroll
        for (int ks = 0; ks < 4; ks++) {
            const int cur = ks & 1, nxt = cur ^ 1;
            // prefetch fragments for next k-step (crosses into next stage at ks==3)
            uint32_t base = (ks < 3) ? (stg + (ks + 1) * 32) : stgn;
            #pragma unroll
            for (int mi = 0; mi < 4; mi++) ldm4(a[nxt][mi], base + aoff[mi]);
            #pragma unroll
            for (int nj = 0; nj < 4; nj++) {
                uint32_t r[4];
                ldm4(r, base + boff[nj]);
                b[nxt][nj*2][0] = r[0]; b[nxt][nj*2][1] = r[1];
                b[nxt][nj*2+1][0] = r[2]; b[nxt][nj*2+1][1] = r[3];
            }
            // compute on current fragments
            #pragma unroll
            for (int mi = 0; mi < 4; mi++)
                #pragma unroll
                for (int ni = 0; ni < 8; ni++)
                    mma16816(c[mi][ni], a[cur][mi], b[cur][ni]);
        }
        s = s1;
    }

    // ---------------- epilogue: out = D * s_x[m] + bias[n] -----------------
    int qr = lane >> 2, qc = lane & 3;
    #pragma unroll
    for (int mi = 0; mi < 4; mi++) {
        int row0 = m0 + wm * 64 + mi * 16 + qr;
        float sx0 = g_sx[row0], sx1 = g_sx[row0 + 8];
        #pragma unroll
        for (int ni = 0; ni < 8; ni++) {
            int col = n0 + wn * 64 + ni * 8 + 2 * qc;
            float2 bv = *(const float2*)(bias + col);
            float2 o0, o1;
            o0.x = c[mi][ni][0] * sx0 + bv.x;
            o0.y = c[mi][ni][1] * sx0 + bv.y;
            o1.x = c[mi][ni][2] * sx1 + bv.x;
            o1.y = c[mi][ni][3] * sx1 + bv.y;
            *(float2*)(out + (size_t)row0 * DOUT + col) = o0;
            *(float2*)(out + (size_t)(row0 + 8) * DOUT + col) = o1;
        }
    }
}

// ------------------------- launch ------------------------------------------
extern "C" void kernel_launch(void* const* d_in, const int* in_sizes, int n_in,
                              void* d_out, int out_size) {
    (void)in_sizes; (void)n_in; (void)out_size;
    const float* x    = (const float*)d_in[0];
    const float* w    = (const float*)d_in[1];
    const float* bias = (const float*)d_in[2];
    const float* ls   = (const float*)d_in[3];
    float* out = (float*)d_out;

    k_scale<<<16, 256>>>(ls);
    k_wq<<<(DOUT * NGRP) / 8, 256>>>(w);
    k_aq<<<MTOT, 256>>>(x);

    cudaFuncSetAttribute(k_gemm, cudaFuncAttributeMaxDynamicSharedMemorySize, SMEM_TOTAL);
    k_gemm<<<(MTOT / MT) * (DOUT / NT), 128, SMEM_TOTAL>>>(bias, out);
}

// round 8
// speedup vs baseline: 1.3792x; 1.0211x over previous
#include <cuda_runtime.h>
#include <cuda_fp16.h>
#include <cstdint>

// Problem dims (fixed by reference)
#define DIN   4096
#define DOUT  4096
#define MTOT  8192
#define QG    128
#define NGRP  (DIN / QG)

// GEMM tiling: CTA 128x128, 4 warps (2x2), warp tile 64x64, KB=64, 3 stages
#define MT     128
#define NT     128
#define KB     64
#define NKIT   (DIN / KB)     // 64
#define STAGES 3
#define ROWB   144            // 128B data + 16B pad (odd multiple of 16)
#define STG_BYTES ((MT + NT) * ROWB)        // 36864
#define SMEM_TOTAL (STAGES * STG_BYTES)     // 110592

// ------------------------- device scratch (no cudaMalloc allowed) ----------
__device__ __half g_xq[(size_t)MTOT * DIN];   // quantized activations (exact ints in fp16)
__device__ __half g_wq[(size_t)DOUT * DIN];   // dequantized weights in fp16
__device__ float  g_sx[MTOT];                 // per-token activation scale
__device__ float  g_scale[DIN];               // clip(exp(log_scale))

// ------------------------- helpers -----------------------------------------
__device__ __forceinline__ uint32_t smem_u32(const void* p) {
    uint32_t a;
    asm("{ .reg .u64 t; cvta.to.shared.u64 t, %1; cvt.u32.u64 %0, t; }" : "=r"(a) : "l"(p));
    return a;
}
__device__ __forceinline__ void cp16(uint32_t dst, const void* src) {
    asm volatile("cp.async.cg.shared.global [%0], [%1], 16;" :: "r"(dst), "l"(src));
}
__device__ __forceinline__ void ldm4(uint32_t* r, uint32_t a) {
    asm volatile("ldmatrix.sync.aligned.m8n8.x4.shared.b16 {%0,%1,%2,%3}, [%4];"
                 : "=r"(r[0]), "=r"(r[1]), "=r"(r[2]), "=r"(r[3]) : "r"(a));
}
__device__ __forceinline__ void mma16816(float* c, const uint32_t* a, const uint32_t* b) {
    asm volatile(
        "mma.sync.aligned.m16n8k16.row.col.f32.f16.f16.f32 "
        "{%0,%1,%2,%3}, {%4,%5,%6,%7}, {%8,%9}, {%0,%1,%2,%3};"
        : "+f"(c[0]), "+f"(c[1]), "+f"(c[2]), "+f"(c[3])
        : "r"(a[0]), "r"(a[1]), "r"(a[2]), "r"(a[3]), "r"(b[0]), "r"(b[1]));
}

// ------------------------- kernel 1: scale ---------------------------------
__global__ void k_scale(const float* __restrict__ ls) {
    int i = blockIdx.x * blockDim.x + threadIdx.x;
    if (i < DIN) {
        float s = expf(ls[i]);
        g_scale[i] = fminf(fmaxf(s, 1e-4f), 1e4f);
    }
}

// ------------------------- kernel 2: weight fake-quant -> fp16 -------------
__global__ __launch_bounds__(256) void k_wq(const float* __restrict__ w) {
    int wid = threadIdx.x >> 5, lane = threadIdx.x & 31;
    int gid = blockIdx.x * 8 + wid;
    int row = gid >> 5;
    int grp = gid & 31;
    int k0  = grp * QG + lane * 4;

    float4 wv = *(const float4*)(w + (size_t)row * DIN + k0);
    float4 sc = *(const float4*)(g_scale + k0);
    float v0 = wv.x * sc.x, v1 = wv.y * sc.y, v2 = wv.z * sc.z, v3 = wv.w * sc.w;

    float mx = fmaxf(fmaxf(v0, v1), fmaxf(v2, v3));
    float mn = fminf(fminf(v0, v1), fminf(v2, v3));
    #pragma unroll
    for (int o = 16; o; o >>= 1) {
        mx = fmaxf(mx, __shfl_xor_sync(0xFFFFFFFFu, mx, o));
        mn = fminf(mn, __shfl_xor_sync(0xFFFFFFFFu, mn, o));
    }
    float s = fmaxf(mx - mn, 1e-5f) / 15.0f;
    float z = fminf(fmaxf(-rintf(mn / s), 0.0f), 15.0f);

    float q0 = (fminf(fmaxf(rintf(v0 / s) + z, 0.0f), 15.0f) - z) * s;
    float q1 = (fminf(fmaxf(rintf(v1 / s) + z, 0.0f), 15.0f) - z) * s;
    float q2 = (fminf(fmaxf(rintf(v2 / s) + z, 0.0f), 15.0f) - z) * s;
    float q3 = (fminf(fmaxf(rintf(v3 / s) + z, 0.0f), 15.0f) - z) * s;

    __half2* dst = (__half2*)(g_wq + (size_t)row * DIN + k0);
    dst[0] = __halves2half2(__float2half_rn(q0), __float2half_rn(q1));
    dst[1] = __halves2half2(__float2half_rn(q2), __float2half_rn(q3));
}

// ------------------------- kernel 3: activation fake-quant -----------------
__global__ __launch_bounds__(256) void k_aq(const float* __restrict__ x) {
    int t = blockIdx.x, tid = threadIdx.x;
    int wid = tid >> 5, lane = tid & 31;
    __shared__ float red[8];

    float v[16];
    float m = 0.0f;
    #pragma unroll
    for (int i = 0; i < 4; i++) {
        int k = (i * 256 + tid) * 4;
        float4 xv = *(const float4*)(x + (size_t)t * DIN + k);
        float4 sc = *(const float4*)(g_scale + k);
        v[i * 4 + 0] = xv.x / sc.x;
        v[i * 4 + 1] = xv.y / sc.y;
        v[i * 4 + 2] = xv.z / sc.z;
        v[i * 4 + 3] = xv.w / sc.w;
        m = fmaxf(m, fmaxf(fmaxf(fabsf(v[i*4+0]), fabsf(v[i*4+1])),
                           fmaxf(fabsf(v[i*4+2]), fabsf(v[i*4+3]))));
    }
    #pragma unroll
    for (int o = 16; o; o >>= 1) m = fmaxf(m, __shfl_xor_sync(0xFFFFFFFFu, m, o));
    if (lane == 0) red[wid] = m;
    __syncthreads();
    if (wid == 0) {
        float tmx = red[lane & 7];
        #pragma unroll
        for (int o = 4; o; o >>= 1) tmx = fmaxf(tmx, __shfl_xor_sync(0xFFFFFFFFu, tmx, o));
        if (lane == 0) red[0] = tmx;
    }
    __syncthreads();
    float s = fmaxf(red[0], 1e-5f) / 127.0f;
    if (tid == 0) g_sx[t] = s;

    #pragma unroll
    for (int i = 0; i < 4; i++) {
        int k = (i * 256 + tid) * 4;
        float q0 = fminf(fmaxf(rintf(v[i*4+0] / s), -128.0f), 127.0f);
        float q1 = fminf(fmaxf(rintf(v[i*4+1] / s), -128.0f), 127.0f);
        float q2 = fminf(fmaxf(rintf(v[i*4+2] / s), -128.0f), 127.0f);
        float q3 = fminf(fmaxf(rintf(v[i*4+3] / s), -128.0f), 127.0f);
        __half2* dst = (__half2*)(g_xq + (size_t)t * DIN + k);
        dst[0] = __halves2half2(__float2half_rn(q0), __float2half_rn(q1));
        dst[1] = __halves2half2(__float2half_rn(q2), __float2half_rn(q3));
    }
}

// ------------------------- kernel 4: GEMM (mma.sync + cp.async, frag-pipelined,
//                            interleaved copy issue) -------------------------
// per stage (128 threads): A 128 rows x 128B + B 128 rows x 128B = 16 cp16/thr,
// issued as 4 cp16 per k-step inside the compute loop.
__device__ __forceinline__ void issue_quarter(uint32_t sA, uint32_t sB,
                                              const __half* Ag, const __half* Bg,
                                              int q, int tid) {
    #pragma unroll
    for (int j = 0; j < 2; j++) {          // A chunks 2q, 2q+1
        int seg = tid + (q * 2 + j) * 128;
        int r = seg >> 3, c = seg & 7;
        cp16(sA + r * ROWB + c * 16, Ag + (size_t)r * DIN + c * 8);
    }
    #pragma unroll
    for (int j = 0; j < 2; j++) {          // B chunks 2q, 2q+1
        int seg = tid + (q * 2 + j) * 128;
        int r = seg >> 3, c = seg & 7;
        cp16(sB + r * ROWB + c * 16, Bg + (size_t)r * DIN + c * 8);
    }
}

__device__ __forceinline__ void issue_stage_full(uint32_t sb, int m0, int n0, int kb,
                                                 int s, int tid) {
    uint32_t sA = sb + s * STG_BYTES;
    uint32_t sB = sA + MT * ROWB;
    const __half* Ag = g_xq + (size_t)m0 * DIN + kb * KB;
    const __half* Bg = g_wq + (size_t)n0 * DIN + kb * KB;
    #pragma unroll
    for (int q = 0; q < 4; q++) issue_quarter(sA, sB, Ag, Bg, q, tid);
    asm volatile("cp.async.commit_group;" ::: "memory");
}

__global__ __launch_bounds__(128, 2) void k_gemm(const float* __restrict__ bias,
                                                 float* __restrict__ out) {
    extern __shared__ char smem[];
    const uint32_t sb = smem_u32(smem);
    int tid = threadIdx.x, lane = tid & 31, wid = tid >> 5;
    int wm = wid & 1, wn = wid >> 1;          // warp grid 2(m) x 2(n), warp tile 64x64
    int bid = blockIdx.x;
    int nt = bid & 31, mt = bid >> 5;
    int m0 = mt * MT, n0 = nt * NT;

    // precomputed per-thread ldmatrix offsets (within a stage)
    uint32_t aoff[4], boff[4];
    #pragma unroll
    for (int mi = 0; mi < 4; mi++)
        aoff[mi] = (uint32_t)(wm * 64 + mi * 16 + (lane & 15)) * ROWB + ((lane >> 4) << 4);
    {
        int g = lane >> 3;
        #pragma unroll
        for (int nj = 0; nj < 4; nj++)
            boff[nj] = (uint32_t)(wn * 64 + nj * 16 + ((g >> 1) << 3) + (lane & 7)) * ROWB
                     + ((g & 1) << 4) + MT * ROWB;
    }

    // prologue: stages 0,1 (full bursts, nothing to overlap yet)
    issue_stage_full(sb, m0, n0, 0, 0, tid);
    issue_stage_full(sb, m0, n0, 1, 1, tid);

    float c[4][8][4];
    #pragma unroll
    for (int i = 0; i < 4; i++)
        #pragma unroll
        for (int j = 0; j < 8; j++)
            #pragma unroll
            for (int k = 0; k < 4; k++) c[i][j][k] = 0.0f;

    uint32_t a[2][4][4], b[2][8][2];
    int s = 0;
    for (int kb = 0; kb < NKIT; kb++) {
        // stages kb and kb+1 are complete after this wait+sync
        asm volatile("cp.async.wait_group 0;" ::: "memory");
        __syncthreads();

        uint32_t stg  = sb + s * STG_BYTES;
        int s1 = s + 1; if (s1 >= STAGES) s1 -= STAGES;
        uint32_t stgn = sb + s1 * STG_BYTES;

        // stage kb+2 target + sources (issued in quarters inside ks loop)
        const bool do_issue = (kb + 2 < NKIT);
        int s2 = s + 2; if (s2 >= STAGES) s2 -= STAGES;
        uint32_t isA = sb + s2 * STG_BYTES;
        uint32_t isB = isA + MT * ROWB;
        const __half* Ag = g_xq + (size_t)m0 * DIN + (kb + 2) * KB;
        const __half* Bg = g_wq + (size_t)n0 * DIN + (kb + 2) * KB;

        if (kb == 0) {   // initial fragment load (stage 0, ks 0) into buf 0
            #pragma unroll
            for (int mi = 0; mi < 4; mi++) ldm4(a[0][mi], stg + aoff[mi]);
            #pragma unroll
            for (int nj = 0; nj < 4; nj++) {
                uint32_t r[4];
                ldm4(r, stg + boff[nj]);
                b[0][nj*2][0] = r[0]; b[0][nj*2][1] = r[1];
                b[0][nj*2+1][0] = r[2]; b[0][nj*2+1][1] = r[3];
            }
        }

        #pragma unroll
        for (int ks = 0; ks < 4; ks++) {
            const int cur = ks & 1, nxt = cur ^ 1;
            // interleaved async-copy issue for stage kb+2 (4 cp16 per ks)
            if (do_issue) issue_quarter(isA, isB, Ag, Bg, ks, tid);
            // prefetch fragments for next k-step (crosses into next stage at ks==3)
            uint32_t base = (ks < 3) ? (stg + (ks + 1) * 32) : stgn;
            #pragma unroll
            for (int mi = 0; mi < 4; mi++) ldm4(a[nxt][mi], base + aoff[mi]);
            #pragma unroll
            for (int nj = 0; nj < 4; nj++) {
                uint32_t r[4];
                ldm4(r, base + boff[nj]);
                b[nxt][nj*2][0] = r[0]; b[nxt][nj*2][1] = r[1];
                b[nxt][nj*2+1][0] = r[2]; b[nxt][nj*2+1][1] = r[3];
            }
            // compute on current fragments
            #pragma unroll
            for (int mi = 0; mi < 4; mi++)
                #pragma unroll
                for (int ni = 0; ni < 8; ni++)
                    mma16816(c[mi][ni], a[cur][mi], b[cur][ni]);
        }
        asm volatile("cp.async.commit_group;" ::: "memory");   // one group per kb
        s = s1;
    }

    // ---------------- epilogue: out = D * s_x[m] + bias[n] -----------------
    int qr = lane >> 2, qc = lane & 3;
    #pragma unroll
    for (int mi = 0; mi < 4; mi++) {
        int row0 = m0 + wm * 64 + mi * 16 + qr;
        float sx0 = g_sx[row0], sx1 = g_sx[row0 + 8];
        #pragma unroll
        for (int ni = 0; ni < 8; ni++) {
            int col = n0 + wn * 64 + ni * 8 + 2 * qc;
            float2 bv = *(const float2*)(bias + col);
            float2 o0, o1;
            o0.x = c[mi][ni][0] * sx0 + bv.x;
            o0.y = c[mi][ni][1] * sx0 + bv.y;
            o1.x = c[mi][ni][2] * sx1 + bv.x;
            o1.y = c[mi][ni][3] * sx1 + bv.y;
            *(float2*)(out + (size_t)row0 * DOUT + col) = o0;
            *(float2*)(out + (size_t)(row0 + 8) * DOUT + col) = o1;
        }
    }
}

// ------------------------- launch ------------------------------------------
extern "C" void kernel_launch(void* const* d_in, const int* in_sizes, int n_in,
                              void* d_out, int out_size) {
    (void)in_sizes; (void)n_in; (void)out_size;
    const float* x    = (const float*)d_in[0];
    const float* w    = (const float*)d_in[1];
    const float* bias = (const float*)d_in[2];
    const float* ls   = (const float*)d_in[3];
    float* out = (float*)d_out;

    k_scale<<<16, 256>>>(ls);
    k_wq<<<(DOUT * NGRP) / 8, 256>>>(w);
    k_aq<<<MTOT, 256>>>(x);

    cudaFuncSetAttribute(k_gemm, cudaFuncAttributeMaxDynamicSharedMemorySize, SMEM_TOTAL);
    k_gemm<<<(MTOT / MT) * (DOUT / NT), 128, SMEM_TOTAL>>>(bias, out);
}

// round 9
// speedup vs baseline: 1.5126x; 1.0968x over previous
#include <cuda_runtime.h>
#include <cuda_fp16.h>
#include <cstdint>

// Problem dims (fixed by reference)
#define DIN   4096
#define DOUT  4096
#define MTOT  8192
#define QG    128
#define NGRP  (DIN / QG)

// GEMM tiling: CTA 128x128, 4 warps (2x2), warp tile 64x64, KB=64, 3 stages
#define MT     128
#define NT     128
#define KB     64
#define NKIT   (DIN / KB)     // 64
#define STAGES 3
#define ROWB   144            // 128B data + 16B pad (odd multiple of 16)
#define STG_BYTES ((MT + NT) * ROWB)        // 36864
#define SMEM_TOTAL (STAGES * STG_BYTES)     // 110592

// ------------------------- device scratch (no cudaMalloc allowed) ----------
__device__ __half g_xq[(size_t)MTOT * DIN];   // quantized activations (exact ints in fp16)
__device__ __half g_wq[(size_t)DOUT * DIN];   // dequantized weights in fp16
__device__ float  g_sx[MTOT];                 // per-token activation scale
__device__ float  g_scale[DIN];               // clip(exp(log_scale))

// ------------------------- helpers -----------------------------------------
__device__ __forceinline__ uint32_t smem_u32(const void* p) {
    uint32_t a;
    asm("{ .reg .u64 t; cvta.to.shared.u64 t, %1; cvt.u32.u64 %0, t; }" : "=r"(a) : "l"(p));
    return a;
}
__device__ __forceinline__ void cp16(uint32_t dst, const void* src) {
    asm volatile("cp.async.cg.shared.global [%0], [%1], 16;" :: "r"(dst), "l"(src));
}
__device__ __forceinline__ void ldm4(uint32_t* r, uint32_t a) {
    asm volatile("ldmatrix.sync.aligned.m8n8.x4.shared.b16 {%0,%1,%2,%3}, [%4];"
                 : "=r"(r[0]), "=r"(r[1]), "=r"(r[2]), "=r"(r[3]) : "r"(a));
}
__device__ __forceinline__ void mma16816(float* c, const uint32_t* a, const uint32_t* b) {
    asm volatile(
        "mma.sync.aligned.m16n8k16.row.col.f32.f16.f16.f32 "
        "{%0,%1,%2,%3}, {%4,%5,%6,%7}, {%8,%9}, {%0,%1,%2,%3};"
        : "+f"(c[0]), "+f"(c[1]), "+f"(c[2]), "+f"(c[3])
        : "r"(a[0]), "r"(a[1]), "r"(a[2]), "r"(a[3]), "r"(b[0]), "r"(b[1]));
}

// ------------------------- kernel 1: scale ---------------------------------
__global__ void k_scale(const float* __restrict__ ls) {
    int i = blockIdx.x * blockDim.x + threadIdx.x;
    if (i < DIN) {
        float s = expf(ls[i]);
        g_scale[i] = fminf(fmaxf(s, 1e-4f), 1e4f);
    }
}

// ------------------------- kernel 2: weight fake-quant -> fp16 -------------
__global__ __launch_bounds__(256) void k_wq(const float* __restrict__ w) {
    int wid = threadIdx.x >> 5, lane = threadIdx.x & 31;
    int gid = blockIdx.x * 8 + wid;
    int row = gid >> 5;
    int grp = gid & 31;
    int k0  = grp * QG + lane * 4;

    float4 wv = *(const float4*)(w + (size_t)row * DIN + k0);
    float4 sc = *(const float4*)(g_scale + k0);
    float v0 = wv.x * sc.x, v1 = wv.y * sc.y, v2 = wv.z * sc.z, v3 = wv.w * sc.w;

    float mx = fmaxf(fmaxf(v0, v1), fmaxf(v2, v3));
    float mn = fminf(fminf(v0, v1), fminf(v2, v3));
    #pragma unroll
    for (int o = 16; o; o >>= 1) {
        mx = fmaxf(mx, __shfl_xor_sync(0xFFFFFFFFu, mx, o));
        mn = fminf(mn, __shfl_xor_sync(0xFFFFFFFFu, mn, o));
    }
    float s = fmaxf(mx - mn, 1e-5f) / 15.0f;
    float z = fminf(fmaxf(-rintf(mn / s), 0.0f), 15.0f);

    float q0 = (fminf(fmaxf(rintf(v0 / s) + z, 0.0f), 15.0f) - z) * s;
    float q1 = (fminf(fmaxf(rintf(v1 / s) + z, 0.0f), 15.0f) - z) * s;
    float q2 = (fminf(fmaxf(rintf(v2 / s) + z, 0.0f), 15.0f) - z) * s;
    float q3 = (fminf(fmaxf(rintf(v3 / s) + z, 0.0f), 15.0f) - z) * s;

    __half2* dst = (__half2*)(g_wq + (size_t)row * DIN + k0);
    dst[0] = __halves2half2(__float2half_rn(q0), __float2half_rn(q1));
    dst[1] = __halves2half2(__float2half_rn(q2), __float2half_rn(q3));
}

// ------------------------- kernel 3: activation fake-quant -----------------
__global__ __launch_bounds__(256) void k_aq(const float* __restrict__ x) {
    int t = blockIdx.x, tid = threadIdx.x;
    int wid = tid >> 5, lane = tid & 31;
    __shared__ float red[8];

    float v[16];
    float m = 0.0f;
    #pragma unroll
    for (int i = 0; i < 4; i++) {
        int k = (i * 256 + tid) * 4;
        float4 xv = *(const float4*)(x + (size_t)t * DIN + k);
        float4 sc = *(const float4*)(g_scale + k);
        v[i * 4 + 0] = xv.x / sc.x;
        v[i * 4 + 1] = xv.y / sc.y;
        v[i * 4 + 2] = xv.z / sc.z;
        v[i * 4 + 3] = xv.w / sc.w;
        m = fmaxf(m, fmaxf(fmaxf(fabsf(v[i*4+0]), fabsf(v[i*4+1])),
                           fmaxf(fabsf(v[i*4+2]), fabsf(v[i*4+3]))));
    }
    #pragma unroll
    for (int o = 16; o; o >>= 1) m = fmaxf(m, __shfl_xor_sync(0xFFFFFFFFu, m, o));
    if (lane == 0) red[wid] = m;
    __syncthreads();
    if (wid == 0) {
        float tmx = red[lane & 7];
        #pragma unroll
        for (int o = 4; o; o >>= 1) tmx = fmaxf(tmx, __shfl_xor_sync(0xFFFFFFFFu, tmx, o));
        if (lane == 0) red[0] = tmx;
    }
    __syncthreads();
    float s = fmaxf(red[0], 1e-5f) / 127.0f;
    if (tid == 0) g_sx[t] = s;

    #pragma unroll
    for (int i = 0; i < 4; i++) {
        int k = (i * 256 + tid) * 4;
        float q0 = fminf(fmaxf(rintf(v[i*4+0] / s), -128.0f), 127.0f);
        float q1 = fminf(fmaxf(rintf(v[i*4+1] / s), -128.0f), 127.0f);
        float q2 = fminf(fmaxf(rintf(v[i*4+2] / s), -128.0f), 127.0f);
        float q3 = fminf(fmaxf(rintf(v[i*4+3] / s), -128.0f), 127.0f);
        __half2* dst = (__half2*)(g_xq + (size_t)t * DIN + k);
        dst[0] = __halves2half2(__float2half_rn(q0), __float2half_rn(q1));
        dst[1] = __halves2half2(__float2half_rn(q2), __float2half_rn(q3));
    }
}

// ------------------------- kernel 4: GEMM (mma.sync + cp.async, frag-pipelined,
//                            interleaved copy issue, wait_group 1) ----------
__device__ __forceinline__ void issue_quarter(uint32_t sA, uint32_t sB,
                                              const __half* Ag, const __half* Bg,
                                              int q, int tid) {
    #pragma unroll
    for (int j = 0; j < 2; j++) {          // A chunks 2q, 2q+1
        int seg = tid + (q * 2 + j) * 128;
        int r = seg >> 3, c = seg & 7;
        cp16(sA + r * ROWB + c * 16, Ag + (size_t)r * DIN + c * 8);
    }
    #pragma unroll
    for (int j = 0; j < 2; j++) {          // B chunks 2q, 2q+1
        int seg = tid + (q * 2 + j) * 128;
        int r = seg >> 3, c = seg & 7;
        cp16(sB + r * ROWB + c * 16, Bg + (size_t)r * DIN + c * 8);
    }
}

__device__ __forceinline__ void issue_stage_full(uint32_t sb, int m0, int n0, int kb,
                                                 int s, int tid) {
    uint32_t sA = sb + s * STG_BYTES;
    uint32_t sB = sA + MT * ROWB;
    const __half* Ag = g_xq + (size_t)m0 * DIN + kb * KB;
    const __half* Bg = g_wq + (size_t)n0 * DIN + kb * KB;
    #pragma unroll
    for (int q = 0; q < 4; q++) issue_quarter(sA, sB, Ag, Bg, q, tid);
    asm volatile("cp.async.commit_group;" ::: "memory");
}

__global__ __launch_bounds__(128, 2) void k_gemm(const float* __restrict__ bias,
                                                 float* __restrict__ out) {
    extern __shared__ char smem[];
    const uint32_t sb = smem_u32(smem);
    int tid = threadIdx.x, lane = tid & 31, wid = tid >> 5;
    int wm = wid & 1, wn = wid >> 1;          // warp grid 2(m) x 2(n), warp tile 64x64
    int bid = blockIdx.x;
    int nt = bid & 31, mt = bid >> 5;
    int m0 = mt * MT, n0 = nt * NT;

    // precomputed per-thread ldmatrix offsets (within a stage)
    uint32_t aoff[4], boff[4];
    #pragma unroll
    for (int mi = 0; mi < 4; mi++)
        aoff[mi] = (uint32_t)(wm * 64 + mi * 16 + (lane & 15)) * ROWB + ((lane >> 4) << 4);
    {
        int g = lane >> 3;
        #pragma unroll
        for (int nj = 0; nj < 4; nj++)
            boff[nj] = (uint32_t)(wn * 64 + nj * 16 + ((g >> 1) << 3) + (lane & 7)) * ROWB
                     + ((g & 1) << 4) + MT * ROWB;
    }

    // prologue: stages 0,1 (full bursts, nothing to overlap yet)
    issue_stage_full(sb, m0, n0, 0, 0, tid);
    issue_stage_full(sb, m0, n0, 1, 1, tid);

    float c[4][8][4];
    #pragma unroll
    for (int i = 0; i < 4; i++)
        #pragma unroll
        for (int j = 0; j < 8; j++)
            #pragma unroll
            for (int k = 0; k < 4; k++) c[i][j][k] = 0.0f;

    uint32_t a[2][4][4], b[2][8][2];
    int s = 0;
    for (int kb = 0; kb < NKIT; kb++) {
        // Invariant: exactly 2 groups outstanding at loop top (a group is
        // committed every iteration, possibly empty). wait_group 1 -> the
        // older group (stage kb, which we read now) is complete; the newer
        // (stage kb+1) keeps flying for one more full iteration.
        asm volatile("cp.async.wait_group 1;" ::: "memory");
        __syncthreads();

        uint32_t stg = sb + s * STG_BYTES;
        int s1 = s + 1; if (s1 >= STAGES) s1 -= STAGES;

        // stage kb+2 target + sources (issued in quarters inside ks loop)
        const bool do_issue = (kb + 2 < NKIT);
        int s2 = s + 2; if (s2 >= STAGES) s2 -= STAGES;
        uint32_t isA = sb + s2 * STG_BYTES;
        uint32_t isB = isA + MT * ROWB;
        const __half* Ag = g_xq + (size_t)m0 * DIN + (kb + 2) * KB;
        const __half* Bg = g_wq + (size_t)n0 * DIN + (kb + 2) * KB;

        // ks=0 fragment load for this stage (exposed once per iteration;
        // covered by the 7 other warps on the SM)
        #pragma unroll
        for (int mi = 0; mi < 4; mi++) ldm4(a[0][mi], stg + aoff[mi]);
        #pragma unroll
        for (int nj = 0; nj < 4; nj++) {
            uint32_t r[4];
            ldm4(r, stg + boff[nj]);
            b[0][nj*2][0] = r[0]; b[0][nj*2][1] = r[1];
            b[0][nj*2+1][0] = r[2]; b[0][nj*2+1][1] = r[3];
        }

        #pragma unroll
        for (int ks = 0; ks < 4; ks++) {
            const int cur = ks & 1, nxt = cur ^ 1;
            // interleaved async-copy issue for stage kb+2 (4 cp16 per ks)
            if (do_issue) issue_quarter(isA, isB, Ag, Bg, ks, tid);
            // prefetch fragments for next k-step (within this stage only)
            if (ks < 3) {
                uint32_t base = stg + (ks + 1) * 32;
                #pragma unroll
                for (int mi = 0; mi < 4; mi++) ldm4(a[nxt][mi], base + aoff[mi]);
                #pragma unroll
                for (int nj = 0; nj < 4; nj++) {
                    uint32_t r[4];
                    ldm4(r, base + boff[nj]);
                    b[nxt][nj*2][0] = r[0]; b[nxt][nj*2][1] = r[1];
                    b[nxt][nj*2+1][0] = r[2]; b[nxt][nj*2+1][1] = r[3];
                }
            }
            // compute on current fragments
            #pragma unroll
            for (int mi = 0; mi < 4; mi++)
                #pragma unroll
                for (int ni = 0; ni < 8; ni++)
                    mma16816(c[mi][ni], a[cur][mi], b[cur][ni]);
        }
        asm volatile("cp.async.commit_group;" ::: "memory");   // one group per kb
        s = s1;
    }

    // ---------------- epilogue: out = D * s_x[m] + bias[n] -----------------
    int qr = lane >> 2, qc = lane & 3;
    #pragma unroll
    for (int mi = 0; mi < 4; mi++) {
        int row0 = m0 + wm * 64 + mi * 16 + qr;
        float sx0 = g_sx[row0], sx1 = g_sx[row0 + 8];
        #pragma unroll
        for (int ni = 0; ni < 8; ni++) {
            int col = n0 + wn * 64 + ni * 8 + 2 * qc;
            float2 bv = *(const float2*)(bias + col);
            float2 o0, o1;
            o0.x = c[mi][ni][0] * sx0 + bv.x;
            o0.y = c[mi][ni][1] * sx0 + bv.y;
            o1.x = c[mi][ni][2] * sx1 + bv.x;
            o1.y = c[mi][ni][3] * sx1 + bv.y;
            *(float2*)(out + (size_t)row0 * DOUT + col) = o0;
            *(float2*)(out + (size_t)(row0 + 8) * DOUT + col) = o1;
        }
    }
}

// ------------------------- launch ------------------------------------------
extern "C" void kernel_launch(void* const* d_in, const int* in_sizes, int n_in,
                              void* d_out, int out_size) {
    (void)in_sizes; (void)n_in; (void)out_size;
    const float* x    = (const float*)d_in[0];
    const float* w    = (const float*)d_in[1];
    const float* bias = (const float*)d_in[2];
    const float* ls   = (const float*)d_in[3];
    float* out = (float*)d_out;

    k_scale<<<16, 256>>>(ls);
    k_wq<<<(DOUT * NGRP) / 8, 256>>>(w);
    k_aq<<<MTOT, 256>>>(x);

    cudaFuncSetAttribute(k_gemm, cudaFuncAttributeMaxDynamicSharedMemorySize, SMEM_TOTAL);
    k_gemm<<<(MTOT / MT) * (DOUT / NT), 128, SMEM_TOTAL>>>(bias, out);
}

// round 10
// speedup vs baseline: 1.6038x; 1.0603x over previous
#include <cuda_runtime.h>
#include <cuda_fp16.h>
#include <cstdint>

// Problem dims (fixed by reference)
#define DIN   4096
#define DOUT  4096
#define MTOT  8192
#define QG    128
#define NGRP  (DIN / QG)

// GEMM tiling: CTA 128x128, 4 warps (2x2), warp tile 64x64, KB=64, 3 stages
#define MT     128
#define NT     128
#define KB     64
#define NKIT   (DIN / KB)     // 64
#define STAGES 3
#define ROWB   144            // 128B data + 16B pad (odd multiple of 16)
#define STG_BYTES ((MT + NT) * ROWB)        // 36864
#define SMEM_TOTAL (STAGES * STG_BYTES)     // 110592

// ------------------------- device scratch (no cudaMalloc allowed) ----------
__device__ __half g_xq[(size_t)MTOT * DIN];   // quantized activations (exact ints in fp16)
__device__ __half g_wq[(size_t)DOUT * DIN];   // dequantized weights in fp16
__device__ float  g_sx[MTOT];                 // per-token activation scale

// ------------------------- helpers -----------------------------------------
__device__ __forceinline__ uint32_t smem_u32(const void* p) {
    uint32_t a;
    asm("{ .reg .u64 t; cvta.to.shared.u64 t, %1; cvt.u32.u64 %0, t; }" : "=r"(a) : "l"(p));
    return a;
}
__device__ __forceinline__ void cp16(uint32_t dst, const void* src) {
    asm volatile("cp.async.cg.shared.global [%0], [%1], 16;" :: "r"(dst), "l"(src));
}
__device__ __forceinline__ void ldm4(uint32_t* r, uint32_t a) {
    asm volatile("ldmatrix.sync.aligned.m8n8.x4.shared.b16 {%0,%1,%2,%3}, [%4];"
                 : "=r"(r[0]), "=r"(r[1]), "=r"(r[2]), "=r"(r[3]) : "r"(a));
}
__device__ __forceinline__ void mma16816(float* c, const uint32_t* a, const uint32_t* b) {
    asm volatile(
        "mma.sync.aligned.m16n8k16.row.col.f32.f16.f16.f32 "
        "{%0,%1,%2,%3}, {%4,%5,%6,%7}, {%8,%9}, {%0,%1,%2,%3};"
        : "+f"(c[0]), "+f"(c[1]), "+f"(c[2]), "+f"(c[3])
        : "r"(a[0]), "r"(a[1]), "r"(a[2]), "r"(a[3]), "r"(b[0]), "r"(b[1]));
}
__device__ __forceinline__ float clip_exp(float v) {
    return fminf(fmaxf(expf(v), 1e-4f), 1e4f);
}

// ------------------------- kernel 1: weight fake-quant -> fp16 -------------
// one warp per (row, group-of-128); 4 elems/thread; scale inlined
__global__ __launch_bounds__(256) void k_wq(const float* __restrict__ w,
                                            const float* __restrict__ ls) {
    int wid = threadIdx.x >> 5, lane = threadIdx.x & 31;
    int gid = blockIdx.x * 8 + wid;
    int row = gid >> 5;
    int grp = gid & 31;
    int k0  = grp * QG + lane * 4;

    float4 wv = *(const float4*)(w + (size_t)row * DIN + k0);
    float4 lv = *(const float4*)(ls + k0);
    float v0 = wv.x * clip_exp(lv.x), v1 = wv.y * clip_exp(lv.y);
    float v2 = wv.z * clip_exp(lv.z), v3 = wv.w * clip_exp(lv.w);

    float mx = fmaxf(fmaxf(v0, v1), fmaxf(v2, v3));
    float mn = fminf(fminf(v0, v1), fminf(v2, v3));
    #pragma unroll
    for (int o = 16; o; o >>= 1) {
        mx = fmaxf(mx, __shfl_xor_sync(0xFFFFFFFFu, mx, o));
        mn = fminf(mn, __shfl_xor_sync(0xFFFFFFFFu, mn, o));
    }
    float s = fmaxf(mx - mn, 1e-5f) / 15.0f;
    float z = fminf(fmaxf(-rintf(mn / s), 0.0f), 15.0f);

    float q0 = (fminf(fmaxf(rintf(v0 / s) + z, 0.0f), 15.0f) - z) * s;
    float q1 = (fminf(fmaxf(rintf(v1 / s) + z, 0.0f), 15.0f) - z) * s;
    float q2 = (fminf(fmaxf(rintf(v2 / s) + z, 0.0f), 15.0f) - z) * s;
    float q3 = (fminf(fmaxf(rintf(v3 / s) + z, 0.0f), 15.0f) - z) * s;

    __half2* dst = (__half2*)(g_wq + (size_t)row * DIN + k0);
    dst[0] = __halves2half2(__float2half_rn(q0), __float2half_rn(q1));
    dst[1] = __halves2half2(__float2half_rn(q2), __float2half_rn(q3));
}

// ------------------------- kernel 2: activation fake-quant -----------------
__global__ __launch_bounds__(256) void k_aq(const float* __restrict__ x,
                                            const float* __restrict__ ls) {
    int t = blockIdx.x, tid = threadIdx.x;
    int wid = tid >> 5, lane = tid & 31;
    __shared__ float red[8];

    float v[16];
    float m = 0.0f;
    #pragma unroll
    for (int i = 0; i < 4; i++) {
        int k = (i * 256 + tid) * 4;
        float4 xv = *(const float4*)(x + (size_t)t * DIN + k);
        float4 lv = *(const float4*)(ls + k);
        v[i * 4 + 0] = xv.x / clip_exp(lv.x);
        v[i * 4 + 1] = xv.y / clip_exp(lv.y);
        v[i * 4 + 2] = xv.z / clip_exp(lv.z);
        v[i * 4 + 3] = xv.w / clip_exp(lv.w);
        m = fmaxf(m, fmaxf(fmaxf(fabsf(v[i*4+0]), fabsf(v[i*4+1])),
                           fmaxf(fabsf(v[i*4+2]), fabsf(v[i*4+3]))));
    }
    #pragma unroll
    for (int o = 16; o; o >>= 1) m = fmaxf(m, __shfl_xor_sync(0xFFFFFFFFu, m, o));
    if (lane == 0) red[wid] = m;
    __syncthreads();
    if (wid == 0) {
        float tmx = red[lane & 7];
        #pragma unroll
        for (int o = 4; o; o >>= 1) tmx = fmaxf(tmx, __shfl_xor_sync(0xFFFFFFFFu, tmx, o));
        if (lane == 0) red[0] = tmx;
    }
    __syncthreads();
    float s = fmaxf(red[0], 1e-5f) / 127.0f;
    if (tid == 0) g_sx[t] = s;

    #pragma unroll
    for (int i = 0; i < 4; i++) {
        int k = (i * 256 + tid) * 4;
        float q0 = fminf(fmaxf(rintf(v[i*4+0] / s), -128.0f), 127.0f);
        float q1 = fminf(fmaxf(rintf(v[i*4+1] / s), -128.0f), 127.0f);
        float q2 = fminf(fmaxf(rintf(v[i*4+2] / s), -128.0f), 127.0f);
        float q3 = fminf(fmaxf(rintf(v[i*4+3] / s), -128.0f), 127.0f);
        __half2* dst = (__half2*)(g_xq + (size_t)t * DIN + k);
        dst[0] = __halves2half2(__float2half_rn(q0), __float2half_rn(q1));
        dst[1] = __halves2half2(__float2half_rn(q2), __float2half_rn(q3));
    }
}

// ------------------------- kernel 3: GEMM -----------------------------------
__device__ __forceinline__ void issue_quarter(uint32_t sA, uint32_t sB,
                                              const __half* Ag, const __half* Bg,
                                              int q, int tid) {
    #pragma unroll
    for (int j = 0; j < 2; j++) {          // A chunks 2q, 2q+1
        int seg = tid + (q * 2 + j) * 128;
        int r = seg >> 3, c = seg & 7;
        cp16(sA + r * ROWB + c * 16, Ag + (size_t)r * DIN + c * 8);
    }
    #pragma unroll
    for (int j = 0; j < 2; j++) {          // B chunks 2q, 2q+1
        int seg = tid + (q * 2 + j) * 128;
        int r = seg >> 3, c = seg & 7;
        cp16(sB + r * ROWB + c * 16, Bg + (size_t)r * DIN + c * 8);
    }
}

__device__ __forceinline__ void issue_stage_full(uint32_t sb, int m0, int n0, int kb,
                                                 int s, int tid) {
    uint32_t sA = sb + s * STG_BYTES;
    uint32_t sB = sA + MT * ROWB;
    const __half* Ag = g_xq + (size_t)m0 * DIN + kb * KB;
    const __half* Bg = g_wq + (size_t)n0 * DIN + kb * KB;
    #pragma unroll
    for (int q = 0; q < 4; q++) issue_quarter(sA, sB, Ag, Bg, q, tid);
    asm volatile("cp.async.commit_group;" ::: "memory");
}

__global__ __launch_bounds__(128, 2) void k_gemm(const float* __restrict__ bias,
                                                 float* __restrict__ out) {
    extern __shared__ char smem[];
    const uint32_t sb = smem_u32(smem);
    int tid = threadIdx.x, lane = tid & 31, wid = tid >> 5;
    int wm = wid & 1, wn = wid >> 1;          // warp grid 2(m) x 2(n), warp tile 64x64
    int bid = blockIdx.x;
    int nt = bid & 31, mt = bid >> 5;
    int m0 = mt * MT, n0 = nt * NT;

    // precomputed per-thread ldmatrix offsets (within a stage)
    uint32_t aoff[4], boff[4];
    #pragma unroll
    for (int mi = 0; mi < 4; mi++)
        aoff[mi] = (uint32_t)(wm * 64 + mi * 16 + (lane & 15)) * ROWB + ((lane >> 4) << 4);
    {
        int g = lane >> 3;
        #pragma unroll
        for (int nj = 0; nj < 4; nj++)
            boff[nj] = (uint32_t)(wn * 64 + nj * 16 + ((g >> 1) << 3) + (lane & 7)) * ROWB
                     + ((g & 1) << 4) + MT * ROWB;
    }

    // prologue: stages 0,1
    issue_stage_full(sb, m0, n0, 0, 0, tid);
    issue_stage_full(sb, m0, n0, 1, 1, tid);

    float c[4][8][4];
    #pragma unroll
    for (int i = 0; i < 4; i++)
        #pragma unroll
        for (int j = 0; j < 8; j++)
            #pragma unroll
            for (int k = 0; k < 4; k++) c[i][j][k] = 0.0f;

    uint32_t a[2][4][4], b[2][8][2];

    // wait stage 0, load its ks0 fragments into buf 0
    asm volatile("cp.async.wait_group 1;" ::: "memory");
    __syncthreads();
    {
        uint32_t stg0 = sb;
        #pragma unroll
        for (int mi = 0; mi < 4; mi++) ldm4(a[0][mi], stg0 + aoff[mi]);
        #pragma unroll
        for (int nj = 0; nj < 4; nj++) {
            uint32_t r[4];
            ldm4(r, stg0 + boff[nj]);
            b[0][nj*2][0] = r[0]; b[0][nj*2][1] = r[1];
            b[0][nj*2+1][0] = r[2]; b[0][nj*2+1][1] = r[3];
        }
    }

    int s = 0;
    for (int kb = 0; kb < NKIT; kb++) {
        uint32_t stg = sb + s * STG_BYTES;
        int s1 = s + 1; if (s1 >= STAGES) s1 -= STAGES;
        uint32_t stgn = sb + s1 * STG_BYTES;

        const bool do_issue = (kb + 2 < NKIT);
        int s2 = s + 2; if (s2 >= STAGES) s2 -= STAGES;
        uint32_t isA = sb + s2 * STG_BYTES;
        uint32_t isB = isA + MT * ROWB;
        const __half* Ag = g_xq + (size_t)m0 * DIN + (kb + 2) * KB;
        const __half* Bg = g_wq + (size_t)n0 * DIN + (kb + 2) * KB;

        // ks = 0..2 : copy quarter, in-stage frag prefetch, mma
        #pragma unroll
        for (int ks = 0; ks < 3; ks++) {
            const int cur = ks & 1, nxt = cur ^ 1;
            if (do_issue) issue_quarter(isA, isB, Ag, Bg, ks, tid);
            uint32_t base = stg + (ks + 1) * 32;
            #pragma unroll
            for (int mi = 0; mi < 4; mi++) ldm4(a[nxt][mi], base + aoff[mi]);
            #pragma unroll
            for (int nj = 0; nj < 4; nj++) {
                uint32_t r[4];
                ldm4(r, base + boff[nj]);
                b[nxt][nj*2][0] = r[0]; b[nxt][nj*2][1] = r[1];
                b[nxt][nj*2+1][0] = r[2]; b[nxt][nj*2+1][1] = r[3];
            }
            #pragma unroll
            for (int mi = 0; mi < 4; mi++)
                #pragma unroll
                for (int ni = 0; ni < 8; ni++)
                    mma16816(c[mi][ni], a[cur][mi], b[cur][ni]);
        }

        // mid-iteration barrier: stage kb+1's group (committed one iteration
        // ago) retires; its data becomes visible to all threads. Also the WAR
        // fence for the buffer the ks0..q3 copies overwrite.
        asm volatile("cp.async.wait_group 0;" ::: "memory");
        __syncthreads();

        // ks = 3 : copy quarter, CROSS-STAGE ks0 frag prefetch, mma
        {
            if (do_issue) issue_quarter(isA, isB, Ag, Bg, 3, tid);
            if (kb + 1 < NKIT) {
                #pragma unroll
                for (int mi = 0; mi < 4; mi++) ldm4(a[0][mi], stgn + aoff[mi]);
                #pragma unroll
                for (int nj = 0; nj < 4; nj++) {
                    uint32_t r[4];
                    ldm4(r, stgn + boff[nj]);
                    b[0][nj*2][0] = r[0]; b[0][nj*2][1] = r[1];
                    b[0][nj*2+1][0] = r[2]; b[0][nj*2+1][1] = r[3];
                }
            }
            #pragma unroll
            for (int mi = 0; mi < 4; mi++)
                #pragma unroll
                for (int ni = 0; ni < 8; ni++)
                    mma16816(c[mi][ni], a[1][mi], b[1][ni]);
        }
        asm volatile("cp.async.commit_group;" ::: "memory");   // one group per kb
        s = s1;
    }

    // ---------------- epilogue: out = D * s_x[m] + bias[n] -----------------
    int qr = lane >> 2, qc = lane & 3;
    #pragma unroll
    for (int mi = 0; mi < 4; mi++) {
        int row0 = m0 + wm * 64 + mi * 16 + qr;
        float sx0 = g_sx[row0], sx1 = g_sx[row0 + 8];
        #pragma unroll
        for (int ni = 0; ni < 8; ni++) {
            int col = n0 + wn * 64 + ni * 8 + 2 * qc;
            float2 bv = *(const float2*)(bias + col);
            float2 o0, o1;
            o0.x = c[mi][ni][0] * sx0 + bv.x;
            o0.y = c[mi][ni][1] * sx0 + bv.y;
            o1.x = c[mi][ni][2] * sx1 + bv.x;
            o1.y = c[mi][ni][3] * sx1 + bv.y;
            *(float2*)(out + (size_t)row0 * DOUT + col) = o0;
            *(float2*)(out + (size_t)(row0 + 8) * DOUT + col) = o1;
        }
    }
}

// ------------------------- launch ------------------------------------------
extern "C" void kernel_launch(void* const* d_in, const int* in_sizes, int n_in,
                              void* d_out, int out_size) {
    (void)in_sizes; (void)n_in; (void)out_size;
    const float* x    = (const float*)d_in[0];
    const float* w    = (const float*)d_in[1];
    const float* bias = (const float*)d_in[2];
    const float* ls   = (const float*)d_in[3];
    float* out = (float*)d_out;

    k_wq<<<(DOUT * NGRP) / 8, 256>>>(w, ls);
    k_aq<<<MTOT, 256>>>(x, ls);

    cudaFuncSetAttribute(k_gemm, cudaFuncAttributeMaxDynamicSharedMemorySize, SMEM_TOTAL);
    k_gemm<<<(MTOT / MT) * (DOUT / NT), 128, SMEM_TOTAL>>>(bias, out);
}

// round 11
// speedup vs baseline: 1.6730x; 1.0431x over previous
#include <cuda_runtime.h>
#include <cuda_fp16.h>
#include <cstdint>

// Problem dims (fixed by reference)
#define DIN   4096
#define DOUT  4096
#define MTOT  8192
#define QG    128
#define NGRP  (DIN / QG)

// GEMM tiling: CTA 128x128, 4 warps (2x2), warp tile 64x64, KB=64, 3 stages
#define MT     128
#define NT     128
#define KB     64
#define NKIT   (DIN / KB)     // 64
#define STAGES 3
#define ROWB   144            // 128B data + 16B pad (odd multiple of 16)
#define STG_BYTES ((MT + NT) * ROWB)        // 36864
#define SMEM_TOTAL (STAGES * STG_BYTES)     // 110592

// ------------------------- device scratch (no cudaMalloc allowed) ----------
__device__ __half g_xq[(size_t)MTOT * DIN];   // quantized activations (exact ints in fp16)
__device__ __half g_wq[(size_t)DOUT * DIN];   // dequantized weights in fp16
__device__ float  g_sx[MTOT];                 // per-token activation scale
__device__ float  g_scale[DIN];               // clip(exp(log_scale))
__device__ float  g_rscale[DIN];              // 1 / clip(exp(log_scale))

// ------------------------- helpers -----------------------------------------
__device__ __forceinline__ uint32_t smem_u32(const void* p) {
    uint32_t a;
    asm("{ .reg .u64 t; cvta.to.shared.u64 t, %1; cvt.u32.u64 %0, t; }" : "=r"(a) : "l"(p));
    return a;
}
__device__ __forceinline__ void cp16(uint32_t dst, const void* src) {
    asm volatile("cp.async.cg.shared.global [%0], [%1], 16;" :: "r"(dst), "l"(src));
}
__device__ __forceinline__ void ldm4(uint32_t* r, uint32_t a) {
    asm volatile("ldmatrix.sync.aligned.m8n8.x4.shared.b16 {%0,%1,%2,%3}, [%4];"
                 : "=r"(r[0]), "=r"(r[1]), "=r"(r[2]), "=r"(r[3]) : "r"(a));
}
__device__ __forceinline__ void mma16816(float* c, const uint32_t* a, const uint32_t* b) {
    asm volatile(
        "mma.sync.aligned.m16n8k16.row.col.f32.f16.f16.f32 "
        "{%0,%1,%2,%3}, {%4,%5,%6,%7}, {%8,%9}, {%0,%1,%2,%3};"
        : "+f"(c[0]), "+f"(c[1]), "+f"(c[2]), "+f"(c[3])
        : "r"(a[0]), "r"(a[1]), "r"(a[2]), "r"(a[3]), "r"(b[0]), "r"(b[1]));
}

// ------------------------- kernel 0: scale (tiny) ---------------------------
__global__ void k_scale(const float* __restrict__ ls) {
    int i = blockIdx.x * blockDim.x + threadIdx.x;
    if (i < DIN) {
        float s = fminf(fmaxf(expf(ls[i]), 1e-4f), 1e4f);
        g_scale[i]  = s;
        g_rscale[i] = 1.0f / s;
    }
}

// ------------------------- kernel 1: weight fake-quant -> fp16 -------------
// one warp per (row, group-of-128); 4 elems/thread
__global__ __launch_bounds__(256) void k_wq(const float* __restrict__ w) {
    int wid = threadIdx.x >> 5, lane = threadIdx.x & 31;
    int gid = blockIdx.x * 8 + wid;
    int row = gid >> 5;
    int grp = gid & 31;
    int k0  = grp * QG + lane * 4;

    float4 wv = *(const float4*)(w + (size_t)row * DIN + k0);
    float4 sc = *(const float4*)(g_scale + k0);
    float v0 = wv.x * sc.x, v1 = wv.y * sc.y, v2 = wv.z * sc.z, v3 = wv.w * sc.w;

    float mx = fmaxf(fmaxf(v0, v1), fmaxf(v2, v3));
    float mn = fminf(fminf(v0, v1), fminf(v2, v3));
    #pragma unroll
    for (int o = 16; o; o >>= 1) {
        mx = fmaxf(mx, __shfl_xor_sync(0xFFFFFFFFu, mx, o));
        mn = fminf(mn, __shfl_xor_sync(0xFFFFFFFFu, mn, o));
    }
    float s = fmaxf(mx - mn, 1e-5f) / 15.0f;
    float z = fminf(fmaxf(-rintf(mn / s), 0.0f), 15.0f);
    float rs = 1.0f / s;

    float q0 = (fminf(fmaxf(rintf(v0 * rs) + z, 0.0f), 15.0f) - z) * s;
    float q1 = (fminf(fmaxf(rintf(v1 * rs) + z, 0.0f), 15.0f) - z) * s;
    float q2 = (fminf(fmaxf(rintf(v2 * rs) + z, 0.0f), 15.0f) - z) * s;
    float q3 = (fminf(fmaxf(rintf(v3 * rs) + z, 0.0f), 15.0f) - z) * s;

    __half2* dst = (__half2*)(g_wq + (size_t)row * DIN + k0);
    dst[0] = __halves2half2(__float2half_rn(q0), __float2half_rn(q1));
    dst[1] = __halves2half2(__float2half_rn(q2), __float2half_rn(q3));
}

// ------------------------- kernel 2: activation fake-quant -----------------
__global__ __launch_bounds__(256) void k_aq(const float* __restrict__ x) {
    int t = blockIdx.x, tid = threadIdx.x;
    int wid = tid >> 5, lane = tid & 31;
    __shared__ float red[8];

    float v[16];
    float m = 0.0f;
    #pragma unroll
    for (int i = 0; i < 4; i++) {
        int k = (i * 256 + tid) * 4;
        float4 xv = *(const float4*)(x + (size_t)t * DIN + k);
        float4 rc = *(const float4*)(g_rscale + k);
        v[i * 4 + 0] = xv.x * rc.x;
        v[i * 4 + 1] = xv.y * rc.y;
        v[i * 4 + 2] = xv.z * rc.z;
        v[i * 4 + 3] = xv.w * rc.w;
        m = fmaxf(m, fmaxf(fmaxf(fabsf(v[i*4+0]), fabsf(v[i*4+1])),
                           fmaxf(fabsf(v[i*4+2]), fabsf(v[i*4+3]))));
    }
    #pragma unroll
    for (int o = 16; o; o >>= 1) m = fmaxf(m, __shfl_xor_sync(0xFFFFFFFFu, m, o));
    if (lane == 0) red[wid] = m;
    __syncthreads();
    if (wid == 0) {
        float tmx = red[lane & 7];
        #pragma unroll
        for (int o = 4; o; o >>= 1) tmx = fmaxf(tmx, __shfl_xor_sync(0xFFFFFFFFu, tmx, o));
        if (lane == 0) red[0] = tmx;
    }
    __syncthreads();
    float s = fmaxf(red[0], 1e-5f) / 127.0f;
    float rs = 127.0f / fmaxf(red[0], 1e-5f);
    if (tid == 0) g_sx[t] = s;

    #pragma unroll
    for (int i = 0; i < 4; i++) {
        int k = (i * 256 + tid) * 4;
        float q0 = fminf(fmaxf(rintf(v[i*4+0] * rs), -128.0f), 127.0f);
        float q1 = fminf(fmaxf(rintf(v[i*4+1] * rs), -128.0f), 127.0f);
        float q2 = fminf(fmaxf(rintf(v[i*4+2] * rs), -128.0f), 127.0f);
        float q3 = fminf(fmaxf(rintf(v[i*4+3] * rs), -128.0f), 127.0f);
        __half2* dst = (__half2*)(g_xq + (size_t)t * DIN + k);
        dst[0] = __halves2half2(__float2half_rn(q0), __float2half_rn(q1));
        dst[1] = __halves2half2(__float2half_rn(q2), __float2half_rn(q3));
    }
}

// ------------------------- kernel 3: GEMM -----------------------------------
__device__ __forceinline__ void issue_quarter(uint32_t sA, uint32_t sB,
                                              const __half* Ag, const __half* Bg,
                                              int q, int tid) {
    #pragma unroll
    for (int j = 0; j < 2; j++) {          // A chunks 2q, 2q+1
        int seg = tid + (q * 2 + j) * 128;
        int r = seg >> 3, c = seg & 7;
        cp16(sA + r * ROWB + c * 16, Ag + (size_t)r * DIN + c * 8);
    }
    #pragma unroll
    for (int j = 0; j < 2; j++) {          // B chunks 2q, 2q+1
        int seg = tid + (q * 2 + j) * 128;
        int r = seg >> 3, c = seg & 7;
        cp16(sB + r * ROWB + c * 16, Bg + (size_t)r * DIN + c * 8);
    }
}

__device__ __forceinline__ void issue_stage_full(uint32_t sb, int m0, int n0, int kb,
                                                 int s, int tid) {
    uint32_t sA = sb + s * STG_BYTES;
    uint32_t sB = sA + MT * ROWB;
    const __half* Ag = g_xq + (size_t)m0 * DIN + kb * KB;
    const __half* Bg = g_wq + (size_t)n0 * DIN + kb * KB;
    #pragma unroll
    for (int q = 0; q < 4; q++) issue_quarter(sA, sB, Ag, Bg, q, tid);
    asm volatile("cp.async.commit_group;" ::: "memory");
}

__global__ __launch_bounds__(128, 2) void k_gemm(const float* __restrict__ bias,
                                                 float* __restrict__ out) {
    extern __shared__ char smem[];
    const uint32_t sb = smem_u32(smem);
    int tid = threadIdx.x, lane = tid & 31, wid = tid >> 5;
    int wm = wid & 1, wn = wid >> 1;          // warp grid 2(m) x 2(n), warp tile 64x64
    int bid = blockIdx.x;
    int nt = bid & 31, mt = bid >> 5;
    int m0 = mt * MT, n0 = nt * NT;

    // precomputed per-thread ldmatrix offsets (within a stage)
    uint32_t aoff[4], boff[4];
    #pragma unroll
    for (int mi = 0; mi < 4; mi++)
        aoff[mi] = (uint32_t)(wm * 64 + mi * 16 + (lane & 15)) * ROWB + ((lane >> 4) << 4);
    {
        int g = lane >> 3;
        #pragma unroll
        for (int nj = 0; nj < 4; nj++)
            boff[nj] = (uint32_t)(wn * 64 + nj * 16 + ((g >> 1) << 3) + (lane & 7)) * ROWB
                     + ((g & 1) << 4) + MT * ROWB;
    }

    // prologue: stages 0,1
    issue_stage_full(sb, m0, n0, 0, 0, tid);
    issue_stage_full(sb, m0, n0, 1, 1, tid);

    float c[4][8][4];
    #pragma unroll
    for (int i = 0; i < 4; i++)
        #pragma unroll
        for (int j = 0; j < 8; j++)
            #pragma unroll
            for (int k = 0; k < 4; k++) c[i][j][k] = 0.0f;

    uint32_t a[2][4][4], b[2][8][2];

    // wait stage 0, load its ks0 fragments into buf 0
    asm volatile("cp.async.wait_group 1;" ::: "memory");
    __syncthreads();
    {
        uint32_t stg0 = sb;
        #pragma unroll
        for (int mi = 0; mi < 4; mi++) ldm4(a[0][mi], stg0 + aoff[mi]);
        #pragma unroll
        for (int nj = 0; nj < 4; nj++) {
            uint32_t r[4];
            ldm4(r, stg0 + boff[nj]);
            b[0][nj*2][0] = r[0]; b[0][nj*2][1] = r[1];
            b[0][nj*2+1][0] = r[2]; b[0][nj*2+1][1] = r[3];
        }
    }

    int s = 0;
    for (int kb = 0; kb < NKIT; kb++) {
        uint32_t stg = sb + s * STG_BYTES;
        int s1 = s + 1; if (s1 >= STAGES) s1 -= STAGES;
        uint32_t stgn = sb + s1 * STG_BYTES;

        const bool do_issue = (kb + 2 < NKIT);
        int s2 = s + 2; if (s2 >= STAGES) s2 -= STAGES;
        uint32_t isA = sb + s2 * STG_BYTES;
        uint32_t isB = isA + MT * ROWB;
        const __half* Ag = g_xq + (size_t)m0 * DIN + (kb + 2) * KB;
        const __half* Bg = g_wq + (size_t)n0 * DIN + (kb + 2) * KB;

        // ks = 0..2 : copy quarter, in-stage frag prefetch, mma
        #pragma unroll
        for (int ks = 0; ks < 3; ks++) {
            const int cur = ks & 1, nxt = cur ^ 1;
            if (do_issue) issue_quarter(isA, isB, Ag, Bg, ks, tid);
            uint32_t base = stg + (ks + 1) * 32;
            #pragma unroll
            for (int mi = 0; mi < 4; mi++) ldm4(a[nxt][mi], base + aoff[mi]);
            #pragma unroll
            for (int nj = 0; nj < 4; nj++) {
                uint32_t r[4];
                ldm4(r, base + boff[nj]);
                b[nxt][nj*2][0] = r[0]; b[nxt][nj*2][1] = r[1];
                b[nxt][nj*2+1][0] = r[2]; b[nxt][nj*2+1][1] = r[3];
            }
            #pragma unroll
            for (int mi = 0; mi < 4; mi++)
                #pragma unroll
                for (int ni = 0; ni < 8; ni++)
                    mma16816(c[mi][ni], a[cur][mi], b[cur][ni]);
        }

        // mid-iteration barrier: stage kb+1's group (committed one iteration
        // ago) retires; its data becomes visible. Also the WAR fence for the
        // buffer the current copies overwrite.
        asm volatile("cp.async.wait_group 0;" ::: "memory");
        __syncthreads();

        // ks = 3 : copy quarter, CROSS-STAGE ks0 frag prefetch, mma
        {
            if (do_issue) issue_quarter(isA, isB, Ag, Bg, 3, tid);
            if (kb + 1 < NKIT) {
                #pragma unroll
                for (int mi = 0; mi < 4; mi++) ldm4(a[0][mi], stgn + aoff[mi]);
                #pragma unroll
                for (int nj = 0; nj < 4; nj++) {
                    uint32_t r[4];
                    ldm4(r, stgn + boff[nj]);
                    b[0][nj*2][0] = r[0]; b[0][nj*2][1] = r[1];
                    b[0][nj*2+1][0] = r[2]; b[0][nj*2+1][1] = r[3];
                }
            }
            #pragma unroll
            for (int mi = 0; mi < 4; mi++)
                #pragma unroll
                for (int ni = 0; ni < 8; ni++)
                    mma16816(c[mi][ni], a[1][mi], b[1][ni]);
        }
        asm volatile("cp.async.commit_group;" ::: "memory");   // one group per kb
        s = s1;
    }

    // ---------------- epilogue: out = D * s_x[m] + bias[n] -----------------
    int qr = lane >> 2, qc = lane & 3;
    #pragma unroll
    for (int mi = 0; mi < 4; mi++) {
        int row0 = m0 + wm * 64 + mi * 16 + qr;
        float sx0 = g_sx[row0], sx1 = g_sx[row0 + 8];
        #pragma unroll
        for (int ni = 0; ni < 8; ni++) {
            int col = n0 + wn * 64 + ni * 8 + 2 * qc;
            float2 bv = *(const float2*)(bias + col);
            float2 o0, o1;
            o0.x = c[mi][ni][0] * sx0 + bv.x;
            o0.y = c[mi][ni][1] * sx0 + bv.y;
            o1.x = c[mi][ni][2] * sx1 + bv.x;
            o1.y = c[mi][ni][3] * sx1 + bv.y;
            *(float2*)(out + (size_t)row0 * DOUT + col) = o0;
            *(float2*)(out + (size_t)(row0 + 8) * DOUT + col) = o1;
        }
    }
}

// ------------------------- launch ------------------------------------------
extern "C" void kernel_launch(void* const* d_in, const int* in_sizes, int n_in,
                              void* d_out, int out_size) {
    (void)in_sizes; (void)n_in; (void)out_size;
    const float* x    = (const float*)d_in[0];
    const float* w    = (const float*)d_in[1];
    const float* bias = (const float*)d_in[2];
    const float* ls   = (const float*)d_in[3];
    float* out = (float*)d_out;

    k_scale<<<16, 256>>>(ls);
    k_wq<<<(DOUT * NGRP) / 8, 256>>>(w);
    k_aq<<<MTOT, 256>>>(x);

    cudaFuncSetAttribute(k_gemm, cudaFuncAttributeMaxDynamicSharedMemorySize, SMEM_TOTAL);
    k_gemm<<<(MTOT / MT) * (DOUT / NT), 128, SMEM_TOTAL>>>(bias, out);
}